// round 6
// baseline (speedup 1.0000x reference)
#include <cuda_runtime.h>
#include <math.h>

#define Bsz 128
#define Tlen 1024
#define Iin 256
#define Hd 512
#define Gd 2048   // 4*Hd
#define NB 256    // persistent grid size (2 units of JT=2 j's per block)

// ---------------- scratch (static device memory; no allocations) ----------------
static __device__ float g_xT [(size_t)Tlen * Iin * Bsz];   // [t][i][b]
static __device__ float g_xg [(size_t)Tlen * Gd  * Bsz];   // [t][g][b]
static __device__ float g_Wcat[(size_t)Gd * 2 * Hd];       // [g][k] = [Wih1|Whh1]
static __device__ float g_bias0[Gd];
static __device__ float g_bias1[Gd];
static __device__ float g_hbuf[2 * (size_t)(2 * Hd) * Bsz]; // 2 buffers of hcatT[1024][128]
static __device__ unsigned g_count;                         // grid-barrier arrivals (monotonic)

__device__ __forceinline__ float sigf(float x) { return 1.0f / (1.0f + expf(-x)); }

#define FMA4(acc, s, v)                                                        \
    acc.x += (s) * (v).x; acc.y += (s) * (v).y;                                \
    acc.z += (s) * (v).z; acc.w += (s) * (v).w;

// ---------------- setup: Wcat, biases, zero state, reset barrier ----------------
__global__ void k_prep(const float* __restrict__ bih0, const float* __restrict__ bhh0,
                       const float* __restrict__ bih1, const float* __restrict__ bhh1,
                       const float* __restrict__ Wih1, const float* __restrict__ Whh1) {
    int i = blockIdx.x * blockDim.x + threadIdx.x;
    if (i < Gd * 2 * Hd) {
        int g = i >> 10;        // / (2*Hd)
        int k = i & 1023;       // % (2*Hd)
        g_Wcat[i] = (k < Hd) ? Wih1[(size_t)g * Hd + k] : Whh1[(size_t)g * Hd + (k - Hd)];
    }
    if (i < Gd) { g_bias0[i] = bih0[i] + bhh0[i]; g_bias1[i] = bih1[i] + bhh1[i]; }
    if (i < 2 * 2 * Hd * Bsz) g_hbuf[i] = 0.0f;
    if (i == 0) g_count = 0u;
}

// ---------------- transpose x[b][t][i] -> xT[t][i][b] ----------------
__global__ void k_tr(const float* __restrict__ x) {
    __shared__ float s[32][129];
    int t = blockIdx.x;
    int ic = blockIdx.y * 32;
    int lane = threadIdx.x & 31;
    int wrp  = threadIdx.x >> 5;
    for (int bb = wrp; bb < Bsz; bb += 8)
        s[lane][bb] = x[((size_t)bb * Tlen + t) * Iin + ic + lane];
    __syncthreads();
    for (int r = 0; r < 16; ++r) {
        int idx = threadIdx.x + r * 256;
        int i = idx >> 7, b = idx & 127;
        g_xT[((size_t)t * Iin + ic + i) * Bsz + b] = s[i][b];
    }
}

// ---------------- input GEMM: xg[t][g][b] = sum_i Wih0[g][i]*xT[t][i][b] + bias0[g] ----------------
__global__ void __launch_bounds__(512) k_xgemm(const float* __restrict__ Wih0) {
    int t = blockIdx.y;
    int w = threadIdx.x >> 5, lane = threadIdx.x & 31;
    int g = blockIdx.x * 16 + w;
    const float*  wr = Wih0 + (size_t)g * Iin;
    const float4* xp = (const float4*)(g_xT + (size_t)t * Iin * Bsz) + lane;
    float b0 = g_bias0[g];
    float4 acc = make_float4(b0, b0, b0, b0);
#pragma unroll 4
    for (int k = 0; k < Iin; k += 4) {
        float4 wv = *(const float4*)(wr + k);
        float4 xa = xp[(k + 0) * 32];
        float4 xb = xp[(k + 1) * 32];
        float4 xc = xp[(k + 2) * 32];
        float4 xd = xp[(k + 3) * 32];
        FMA4(acc, wv.x, xa); FMA4(acc, wv.y, xb);
        FMA4(acc, wv.z, xc); FMA4(acc, wv.w, xd);
    }
    ((float4*)(g_xg + ((size_t)t * Gd + g) * Bsz))[lane] = acc;
}

// ---------------- grid barrier (monotonic counter; all NB blocks co-resident) ----------------
__device__ __forceinline__ void gridbar(unsigned expected) {
    __threadfence();          // publish this thread's prior global stores
    __syncthreads();          // all threads of the block have fenced
    if (threadIdx.x == 0) {
        atomicAdd(&g_count, 1u);
        while (atomicAdd(&g_count, 0u) < expected) { }
    }
    __syncthreads();
}

// ---------------- persistent scan: all 1024 steps, both layers, final FC ----------------
// 256 blocks x 128 threads. Block u owns hidden units j0=2u, j0+1 of BOTH layers.
// Warp w computes gate w (i,f,g,o) for both units. c-state lives in registers.
// h goes through L2 (__ldcg reads; barrier-ordered stores).
__global__ void __launch_bounds__(128, 4) k_scan(const float* __restrict__ Whh0,
                                                 const float* __restrict__ fcw,
                                                 const float* __restrict__ fcb,
                                                 float* __restrict__ out) {
    __shared__ float s_g[4 * 2 * 128];   // [gate][jj][b]
    const int u = blockIdx.x;
    const int w = threadIdx.x >> 5, lane = threadIdx.x & 31;
    const int m = threadIdx.x;
    const int j0 = 2 * u;
    const int col0 = w * Hd + j0;

    const float* wA0 = Whh0  + (size_t)col0 * Hd;
    const float* wA1 = wA0 + Hd;                     // col0+1 row
    const float* wB0 = g_Wcat + (size_t)col0 * (2 * Hd);
    const float* wB1 = wB0 + 2 * Hd;
    const float  bB0 = g_bias1[col0];
    const float  bB1 = g_bias1[col0 + 1];

    float c0a = 0.0f, c0b = 0.0f;   // layer-0 cell state for (j0, m), (j0+1, m)
    float c1a = 0.0f, c1b = 0.0f;   // layer-1 cell state
    unsigned bar = 0;

#pragma unroll 1
    for (int t = 0; t < Tlen; ++t) {
        const float* cur = g_hbuf + (size_t)(t & 1) * (2 * Hd * Bsz);
        float*       nxt = g_hbuf + (size_t)((t + 1) & 1) * (2 * Hd * Bsz);

        // ===== phase A: layer-0 gates for units j0, j0+1 =====
        {
            const float4* hp  = (const float4*)cur + lane;      // rows 0..511 = h0_prev
            const float4* xgp = (const float4*)(g_xg + ((size_t)t * Gd + col0) * Bsz);
            float4 a0 = __ldg(xgp + lane);
            float4 a1 = __ldg(xgp + 32 + lane);
#pragma unroll 4
            for (int k = 0; k < Hd; k += 4) {
                float4 wv0 = __ldg((const float4*)(wA0 + k));
                float4 wv1 = __ldg((const float4*)(wA1 + k));
                float4 h0 = __ldcg(hp + (k + 0) * 32);
                float4 h1 = __ldcg(hp + (k + 1) * 32);
                float4 h2 = __ldcg(hp + (k + 2) * 32);
                float4 h3 = __ldcg(hp + (k + 3) * 32);
                FMA4(a0, wv0.x, h0); FMA4(a0, wv0.y, h1);
                FMA4(a0, wv0.z, h2); FMA4(a0, wv0.w, h3);
                FMA4(a1, wv1.x, h0); FMA4(a1, wv1.y, h1);
                FMA4(a1, wv1.z, h2); FMA4(a1, wv1.w, h3);
            }
            ((float4*)s_g)[(w * 2 + 0) * 32 + lane] = a0;
            ((float4*)s_g)[(w * 2 + 1) * 32 + lane] = a1;
        }
        __syncthreads();
        {
            float gi = s_g[(0 * 2 + 0) * 128 + m];
            float gf = s_g[(1 * 2 + 0) * 128 + m];
            float gg = s_g[(2 * 2 + 0) * 128 + m];
            float go = s_g[(3 * 2 + 0) * 128 + m];
            c0a = sigf(gf) * c0a + sigf(gi) * tanhf(gg);
            nxt[(size_t)(j0 + 0) * Bsz + m] = sigf(go) * tanhf(c0a);

            gi = s_g[(0 * 2 + 1) * 128 + m];
            gf = s_g[(1 * 2 + 1) * 128 + m];
            gg = s_g[(2 * 2 + 1) * 128 + m];
            go = s_g[(3 * 2 + 1) * 128 + m];
            c0b = sigf(gf) * c0b + sigf(gi) * tanhf(gg);
            nxt[(size_t)(j0 + 1) * Bsz + m] = sigf(go) * tanhf(c0b);
        }
        gridbar(++bar * NB);   // h0[t] visible everywhere; s_g reusable

        // ===== phase B: layer-1 gates = [h0_new | h1_prev] @ Wcat^T + bias1 =====
        {
            const float4* hpN = (const float4*)nxt + lane;   // k in [0,512): h0 new
            const float4* hpC = (const float4*)cur + lane;   // k in [512,1024): h1 prev (rows 512..)
            float4 a0 = make_float4(bB0, bB0, bB0, bB0);
            float4 a1 = make_float4(bB1, bB1, bB1, bB1);
#pragma unroll 4
            for (int k = 0; k < Hd; k += 4) {
                float4 wv0 = __ldg((const float4*)(wB0 + k));
                float4 wv1 = __ldg((const float4*)(wB1 + k));
                float4 h0 = __ldcg(hpN + (k + 0) * 32);
                float4 h1 = __ldcg(hpN + (k + 1) * 32);
                float4 h2 = __ldcg(hpN + (k + 2) * 32);
                float4 h3 = __ldcg(hpN + (k + 3) * 32);
                FMA4(a0, wv0.x, h0); FMA4(a0, wv0.y, h1);
                FMA4(a0, wv0.z, h2); FMA4(a0, wv0.w, h3);
                FMA4(a1, wv1.x, h0); FMA4(a1, wv1.y, h1);
                FMA4(a1, wv1.z, h2); FMA4(a1, wv1.w, h3);
            }
#pragma unroll 4
            for (int k = Hd; k < 2 * Hd; k += 4) {
                float4 wv0 = __ldg((const float4*)(wB0 + k));
                float4 wv1 = __ldg((const float4*)(wB1 + k));
                float4 h0 = __ldcg(hpC + (k + 0) * 32);      // row k = 512.. -> h1_prev
                float4 h1 = __ldcg(hpC + (k + 1) * 32);
                float4 h2 = __ldcg(hpC + (k + 2) * 32);
                float4 h3 = __ldcg(hpC + (k + 3) * 32);
                FMA4(a0, wv0.x, h0); FMA4(a0, wv0.y, h1);
                FMA4(a0, wv0.z, h2); FMA4(a0, wv0.w, h3);
                FMA4(a1, wv1.x, h0); FMA4(a1, wv1.y, h1);
                FMA4(a1, wv1.z, h2); FMA4(a1, wv1.w, h3);
            }
            ((float4*)s_g)[(w * 2 + 0) * 32 + lane] = a0;
            ((float4*)s_g)[(w * 2 + 1) * 32 + lane] = a1;
        }
        __syncthreads();
        {
            float gi = s_g[(0 * 2 + 0) * 128 + m];
            float gf = s_g[(1 * 2 + 0) * 128 + m];
            float gg = s_g[(2 * 2 + 0) * 128 + m];
            float go = s_g[(3 * 2 + 0) * 128 + m];
            c1a = sigf(gf) * c1a + sigf(gi) * tanhf(gg);
            nxt[(size_t)(Hd + j0 + 0) * Bsz + m] = sigf(go) * tanhf(c1a);

            gi = s_g[(0 * 2 + 1) * 128 + m];
            gf = s_g[(1 * 2 + 1) * 128 + m];
            gg = s_g[(2 * 2 + 1) * 128 + m];
            go = s_g[(3 * 2 + 1) * 128 + m];
            c1b = sigf(gf) * c1b + sigf(gi) * tanhf(gg);
            nxt[(size_t)(Hd + j0 + 1) * Bsz + m] = sigf(go) * tanhf(c1b);
        }
        gridbar(++bar * NB);   // h1[t] visible; safe to overwrite next step
    }

    // ===== final FC (block 0): logits[b] = h1_final . fc_w + fc_b =====
    // After t=1023, final state buffer index = (1023+1)&1 = 0.
    if (blockIdx.x == 0) {
        const float* hf = g_hbuf;   // buffer 0
        float acc = __ldg(fcb);
#pragma unroll 8
        for (int j = 0; j < Hd; ++j)
            acc += __ldcg(hf + (size_t)(Hd + j) * Bsz + m) * __ldg(fcw + j);
        out[m] = acc;
    }
}

extern "C" void kernel_launch(void* const* d_in, const int* in_sizes, int n_in,
                              void* d_out, int out_size) {
    const float* x    = (const float*)d_in[0];
    const float* Wih0 = (const float*)d_in[1];
    const float* Whh0 = (const float*)d_in[2];
    const float* bih0 = (const float*)d_in[3];
    const float* bhh0 = (const float*)d_in[4];
    const float* Wih1 = (const float*)d_in[5];
    const float* Whh1 = (const float*)d_in[6];
    const float* bih1 = (const float*)d_in[7];
    const float* bhh1 = (const float*)d_in[8];
    const float* fcw  = (const float*)d_in[9];
    const float* fcb  = (const float*)d_in[10];
    float* out = (float*)d_out;

    k_prep<<<(Gd * 2 * Hd) / 256, 256>>>(bih0, bhh0, bih1, bhh1, Wih1, Whh1);

    dim3 gtr(Tlen, Iin / 32);
    k_tr<<<gtr, 256>>>(x);

    dim3 gxg(Gd / 16, Tlen);
    k_xgemm<<<gxg, 512>>>(Wih0);

    k_scan<<<NB, 128>>>(Whh0, fcw, fcb, out);
}

// round 8
// speedup vs baseline: 1.5198x; 1.5198x over previous
#include <cuda_runtime.h>
#include <math.h>
#include <stdint.h>

#define Bsz 128
#define Tlen 1024
#define Iin 256
#define Hd 512
#define Gd 2048   // 4*Hd
#define NB 128    // persistent grid: 32 row-groups x 4 batch-slices
#define NT 256
#define KC 32     // k-chunk staged per cp.async round

// ---------------- scratch (static device memory; no allocations) ----------------
static __device__ __align__(16) float g_xT [(size_t)Tlen * Iin * Bsz];   // [t][i][b]
static __device__ __align__(16) float g_xg [(size_t)Tlen * Gd  * Bsz];   // [t][g][b]
static __device__ __align__(16) float g_Wcat[(size_t)Gd * 2 * Hd];       // [g][k] = [Wih1|Whh1]
static __device__ float g_bias0[Gd];
static __device__ float g_bias1[Gd];
static __device__ __align__(16) float g_hbuf[2 * (size_t)(2 * Hd) * Bsz]; // 2 x [1024 rows][128 b]
static __device__ unsigned g_count;

__device__ __forceinline__ float sigf(float x) { return 1.0f / (1.0f + expf(-x)); }

#define FMA4(acc, s, v)                                                        \
    acc.x += (s) * (v).x; acc.y += (s) * (v).y;                                \
    acc.z += (s) * (v).z; acc.w += (s) * (v).w;

#define CP16(dst, src)                                                         \
    asm volatile("cp.async.cg.shared.global [%0], [%1], 16;\n"                 \
                 :: "r"(dst), "l"(src) : "memory")

__device__ __forceinline__ unsigned su32(const void* p) {
    return (unsigned)__cvta_generic_to_shared(p);
}

// ---------------- setup: Wcat, biases, zero state, reset barrier ----------------
__global__ void k_prep(const float* __restrict__ bih0, const float* __restrict__ bhh0,
                       const float* __restrict__ bih1, const float* __restrict__ bhh1,
                       const float* __restrict__ Wih1, const float* __restrict__ Whh1) {
    int i = blockIdx.x * blockDim.x + threadIdx.x;
    if (i < Gd * 2 * Hd) {
        int g = i >> 10;
        int k = i & 1023;
        g_Wcat[i] = (k < Hd) ? Wih1[(size_t)g * Hd + k] : Whh1[(size_t)g * Hd + (k - Hd)];
    }
    if (i < Gd) { g_bias0[i] = bih0[i] + bhh0[i]; g_bias1[i] = bih1[i] + bhh1[i]; }
    if (i < 2 * 2 * Hd * Bsz) g_hbuf[i] = 0.0f;
    if (i == 0) g_count = 0u;
}

// ---------------- transpose x[b][t][i] -> xT[t][i][b] ----------------
__global__ void k_tr(const float* __restrict__ x) {
    __shared__ float s[32][129];
    int t = blockIdx.x;
    int ic = blockIdx.y * 32;
    int lane = threadIdx.x & 31;
    int wrp  = threadIdx.x >> 5;
    for (int bb = wrp; bb < Bsz; bb += 8)
        s[lane][bb] = x[((size_t)bb * Tlen + t) * Iin + ic + lane];
    __syncthreads();
    for (int r = 0; r < 16; ++r) {
        int idx = threadIdx.x + r * 256;
        int i = idx >> 7, b = idx & 127;
        g_xT[((size_t)t * Iin + ic + i) * Bsz + b] = s[i][b];
    }
}

// ---------------- input GEMM with 4-row register tiling ----------------
__global__ void __launch_bounds__(512) k_xgemm(const float* __restrict__ Wih0) {
    int t = blockIdx.y;
    int w = threadIdx.x >> 5, lane = threadIdx.x & 31;
    int g0 = blockIdx.x * 64 + w * 4;
    const float*  wr = Wih0 + (size_t)g0 * Iin;
    const float4* xp = (const float4*)(g_xT + (size_t)t * Iin * Bsz) + lane;
    float b0 = g_bias0[g0 + 0], b1 = g_bias0[g0 + 1];
    float b2 = g_bias0[g0 + 2], b3 = g_bias0[g0 + 3];
    float4 a0 = make_float4(b0, b0, b0, b0);
    float4 a1 = make_float4(b1, b1, b1, b1);
    float4 a2 = make_float4(b2, b2, b2, b2);
    float4 a3 = make_float4(b3, b3, b3, b3);
#pragma unroll 4
    for (int k = 0; k < Iin; k += 4) {
        float4 xa = xp[(k + 0) * 32];
        float4 xb = xp[(k + 1) * 32];
        float4 xc = xp[(k + 2) * 32];
        float4 xd = xp[(k + 3) * 32];
        float4 w0 = *(const float4*)(wr + 0 * Iin + k);
        float4 w1 = *(const float4*)(wr + 1 * Iin + k);
        float4 w2 = *(const float4*)(wr + 2 * Iin + k);
        float4 w3 = *(const float4*)(wr + 3 * Iin + k);
        FMA4(a0, w0.x, xa); FMA4(a0, w0.y, xb); FMA4(a0, w0.z, xc); FMA4(a0, w0.w, xd);
        FMA4(a1, w1.x, xa); FMA4(a1, w1.y, xb); FMA4(a1, w1.z, xc); FMA4(a1, w1.w, xd);
        FMA4(a2, w2.x, xa); FMA4(a2, w2.y, xb); FMA4(a2, w2.z, xc); FMA4(a2, w2.w, xd);
        FMA4(a3, w3.x, xa); FMA4(a3, w3.y, xb); FMA4(a3, w3.z, xc); FMA4(a3, w3.w, xd);
    }
    ((float4*)(g_xg + ((size_t)t * Gd + g0 + 0) * Bsz))[lane] = a0;
    ((float4*)(g_xg + ((size_t)t * Gd + g0 + 1) * Bsz))[lane] = a1;
    ((float4*)(g_xg + ((size_t)t * Gd + g0 + 2) * Bsz))[lane] = a2;
    ((float4*)(g_xg + ((size_t)t * Gd + g0 + 3) * Bsz))[lane] = a3;
}

// ---------------- grid barrier ----------------
__device__ __forceinline__ void gridbar(unsigned expected) {
    __threadfence();
    __syncthreads();
    if (threadIdx.x == 0) {
        atomicAdd(&g_count, 1u);
        while (atomicAdd(&g_count, 0u) < expected) { }
    }
    __syncthreads();
}

// ---------------- persistent scan ----------------
// 128 blocks x 256 threads. Block = 16 hidden units (64 gate-rows) x 32-batch slice.
// Warp w: gate w>>1, unit sub-group w&1 -> 8 rows. h + weights staged via cp.async
// double buffering; one grid barrier per timestep via [B(t); A(t+1)] pipelining.
__global__ void __launch_bounds__(NT, 2) k_scan(const float* __restrict__ Whh0,
                                                const float* __restrict__ fcw,
                                                const float* __restrict__ fcb,
                                                float* __restrict__ out) {
    __shared__ __align__(16) float s_h[2][KC][32];   // staged h chunk   (8 KB)
    __shared__ __align__(16) float s_w[2][64][KC];   // staged weights   (16 KB)
    __shared__ __align__(16) float s_g[64][32];      // gate exchange    (8 KB)

    const int m = threadIdx.x;
    const int w = m >> 5, lane = m & 31;
    const int ju = blockIdx.x >> 2;          // 0..31 row-group
    const int bu = blockIdx.x & 3;           // 0..3 batch slice
    const int j0 = ju * 16;                  // first hidden unit of this block
    const int b0 = bu * 32;                  // first batch element

    // cp.async duties (per thread)
    const int kRow = m >> 3;                 // 0..31: h row within chunk / weight row 0..31
    const int seg  = m & 7;                  // 16B segment within a 128B row
    const int rW1  = kRow + 32;              // second weight row duty
    const int grow0 = ((kRow >> 4) << 9) + j0 + (kRow & 15);  // global gate-row
    const int grow1 = ((rW1  >> 4) << 9) + j0 + (rW1  & 15);

    // compute rows for this warp: crBase + r, r<8
    const int crBase = ((w >> 1) << 9) + j0 + ((w & 1) << 3);

    // activation mapping: thread -> (unit u0 & u0+8, batch ab)
    const int u0 = m >> 5;                   // 0..7
    const int u1 = u0 + 8;                   // 8..15
    const int ab = m & 31;

    float c0a = 0.f, c0b = 0.f, c1a = 0.f, c1b = 0.f;
    unsigned bar = 0;
    float acc[8];

    auto issue_chunk = [&](int c, int buf, const float* wsrc, int K, const float* hs) {
        CP16(su32(&s_h[buf][kRow][seg * 4]),
             hs + ((size_t)(c * KC + kRow)) * Bsz + b0 + seg * 4);
        CP16(su32(&s_w[buf][kRow][seg * 4]),
             wsrc + (size_t)grow0 * K + c * KC + seg * 4);
        CP16(su32(&s_w[buf][rW1][seg * 4]),
             wsrc + (size_t)grow1 * K + c * KC + seg * 4);
        asm volatile("cp.async.commit_group;\n" ::: "memory");
    };

    // GEMM: acc[r] += sum_k W[crBase+r][k] * h[k][b0+lane]
    // h source: rows kk = c*KC+kRow from hA (c < csplit) else hB (row index = kk directly).
    auto gemm = [&](const float* wsrc, int K, const float* hA, const float* hB, int csplit) {
        const int NC = K / KC;
        issue_chunk(0, 0, wsrc, K, (0 < csplit) ? hA : hB);
        issue_chunk(1, 1, wsrc, K, (1 < csplit) ? hA : hB);
        for (int c = 0; c < NC; ++c) {
            if (c < NC - 1) { asm volatile("cp.async.wait_group 1;\n" ::: "memory"); }
            else            { asm volatile("cp.async.wait_group 0;\n" ::: "memory"); }
            __syncthreads();
            const int cb = c & 1;
#pragma unroll
            for (int k4 = 0; k4 < KC; k4 += 4) {
                float h0v = s_h[cb][k4 + 0][lane];
                float h1v = s_h[cb][k4 + 1][lane];
                float h2v = s_h[cb][k4 + 2][lane];
                float h3v = s_h[cb][k4 + 3][lane];
#pragma unroll
                for (int r = 0; r < 8; ++r) {
                    float4 wv = *(const float4*)&s_w[cb][w * 8 + r][k4];
                    acc[r] = fmaf(wv.x, h0v,
                             fmaf(wv.y, h1v,
                             fmaf(wv.z, h2v,
                             fmaf(wv.w, h3v, acc[r]))));
                }
            }
            __syncthreads();
            if (c + 2 < NC) issue_chunk(c + 2, cb, wsrc, K, (c + 2 < csplit) ? hA : hB);
        }
#pragma unroll
        for (int r = 0; r < 8; ++r) s_g[w * 8 + r][lane] = acc[r];
        __syncthreads();
    };

    // buffers: h0(t) lives in buf[(t+1)&1] rows [0,512); h1(t) in buf[(t+1)&1] rows [512,1024)
    float* const bufs[2] = { g_hbuf, g_hbuf + (size_t)(2 * Hd) * Bsz };

    // ===== A(0): gates = xg[0] + Whh0 @ h0(-1)=0 ; writes h0(0) -> buf1 =====
    {
#pragma unroll
        for (int r = 0; r < 8; ++r)
            acc[r] = g_xg[((size_t)0 * Gd + crBase + r) * Bsz + b0 + lane];
        gemm(Whh0, Hd, bufs[0], bufs[0], 16);
        float* hdst = bufs[1];
        float gi = s_g[0 * 16 + u0][ab], gf = s_g[1 * 16 + u0][ab];
        float gg = s_g[2 * 16 + u0][ab], go = s_g[3 * 16 + u0][ab];
        c0a = sigf(gf) * c0a + sigf(gi) * tanhf(gg);
        hdst[(size_t)(j0 + u0) * Bsz + b0 + ab] = sigf(go) * tanhf(c0a);
        gi = s_g[0 * 16 + u1][ab]; gf = s_g[1 * 16 + u1][ab];
        gg = s_g[2 * 16 + u1][ab]; go = s_g[3 * 16 + u1][ab];
        c0b = sigf(gf) * c0b + sigf(gi) * tanhf(gg);
        hdst[(size_t)(j0 + u1) * Bsz + b0 + ab] = sigf(go) * tanhf(c0b);
    }
    gridbar(++bar * NB);

    for (int t = 0; t < Tlen; ++t) {
        float* bufA = bufs[(t + 1) & 1];   // holds h0(t); receives h1(t) in rows 512+
        float* bufB = bufs[t & 1];         // holds h1(t-1) rows 512+; receives h0(t+1)

        // ===== B(t): gates = bias1 + Wcat @ [h0(t) | h1(t-1)] ; writes h1(t) =====
        {
#pragma unroll
            for (int r = 0; r < 8; ++r) acc[r] = __ldg(&g_bias1[crBase + r]);
            gemm(g_Wcat, 2 * Hd, bufA, bufB, 16);
            float gi = s_g[0 * 16 + u0][ab], gf = s_g[1 * 16 + u0][ab];
            float gg = s_g[2 * 16 + u0][ab], go = s_g[3 * 16 + u0][ab];
            c1a = sigf(gf) * c1a + sigf(gi) * tanhf(gg);
            bufA[(size_t)(Hd + j0 + u0) * Bsz + b0 + ab] = sigf(go) * tanhf(c1a);
            gi = s_g[0 * 16 + u1][ab]; gf = s_g[1 * 16 + u1][ab];
            gg = s_g[2 * 16 + u1][ab]; go = s_g[3 * 16 + u1][ab];
            c1b = sigf(gf) * c1b + sigf(gi) * tanhf(gg);
            bufA[(size_t)(Hd + j0 + u1) * Bsz + b0 + ab] = sigf(go) * tanhf(c1b);
        }

        // ===== A(t+1): gates = xg[t+1] + Whh0 @ h0(t) ; writes h0(t+1) -> bufB =====
        if (t < Tlen - 1) {
#pragma unroll
            for (int r = 0; r < 8; ++r)
                acc[r] = __ldg(&g_xg[((size_t)(t + 1) * Gd + crBase + r) * Bsz + b0 + lane]);
            gemm(Whh0, Hd, bufA, bufA, 16);
            float gi = s_g[0 * 16 + u0][ab], gf = s_g[1 * 16 + u0][ab];
            float gg = s_g[2 * 16 + u0][ab], go = s_g[3 * 16 + u0][ab];
            c0a = sigf(gf) * c0a + sigf(gi) * tanhf(gg);
            bufB[(size_t)(j0 + u0) * Bsz + b0 + ab] = sigf(go) * tanhf(c0a);
            gi = s_g[0 * 16 + u1][ab]; gf = s_g[1 * 16 + u1][ab];
            gg = s_g[2 * 16 + u1][ab]; go = s_g[3 * 16 + u1][ab];
            c0b = sigf(gf) * c0b + sigf(gi) * tanhf(gg);
            bufB[(size_t)(j0 + u1) * Bsz + b0 + ab] = sigf(go) * tanhf(c0b);
        }
        gridbar(++bar * NB);
    }

    // ===== final FC (block 0): h1(1023) lives in buf[(1024)&1]=buf0 rows 512+ =====
    if (blockIdx.x == 0 && m < Bsz) {
        const float* hf = bufs[0];
        float a = __ldg(fcb);
#pragma unroll 8
        for (int j = 0; j < Hd; ++j)
            a += __ldcg(&hf[(size_t)(Hd + j) * Bsz + m]) * __ldg(&fcw[j]);
        out[m] = a;
    }
}

extern "C" void kernel_launch(void* const* d_in, const int* in_sizes, int n_in,
                              void* d_out, int out_size) {
    const float* x    = (const float*)d_in[0];
    const float* Wih0 = (const float*)d_in[1];
    const float* Whh0 = (const float*)d_in[2];
    const float* bih0 = (const float*)d_in[3];
    const float* bhh0 = (const float*)d_in[4];
    const float* Wih1 = (const float*)d_in[5];
    const float* Whh1 = (const float*)d_in[6];
    const float* bih1 = (const float*)d_in[7];
    const float* bhh1 = (const float*)d_in[8];
    const float* fcw  = (const float*)d_in[9];
    const float* fcb  = (const float*)d_in[10];
    float* out = (float*)d_out;

    k_prep<<<(Gd * 2 * Hd) / 256, 256>>>(bih0, bhh0, bih1, bhh1, Wih1, Whh1);

    dim3 gtr(Tlen, Iin / 32);
    k_tr<<<gtr, 256>>>(x);

    dim3 gxg(Gd / 64, Tlen);
    k_xgemm<<<gxg, 512>>>(Wih0);

    k_scan<<<NB, NT>>>(Whh0, fcw, fcb, out);
}

// round 10
// speedup vs baseline: 2.7055x; 1.7802x over previous
#include <cuda_runtime.h>
#include <math.h>
#include <stdint.h>

#define Bsz 128
#define Tlen 1024
#define Iin 256
#define Hd 512
#define Gd 2048      // 4*Hd
#define NBLK 128     // persistent grid: 32 unit-groups x 4 batch-slices
#define NT 256
#define KC 32        // k-chunk per cp.async stage
#define SW 36        // padded stride of s_w rows (floats)
#define SH 36        // padded stride of s_hT rows (floats)
#define SG 34        // padded stride of s_g rows (floats)
#define SMEM_BYTES ((3*64*SW + 3*32*SH + 64*SG) * 4)

// ---------------- scratch (static device memory; no allocations) ----------------
static __device__ __align__(16) float g_xT [(size_t)Tlen * Iin * Bsz];   // [t][i][b]
static __device__ __align__(16) float g_xg [(size_t)Tlen * Gd  * Bsz];   // [t][g][b]
static __device__ __align__(16) float g_Wh0c[(size_t)Gd * Hd];           // Whh0 tf32-rounded
static __device__ __align__(16) float g_Wcat[(size_t)Gd * 2 * Hd];       // [Wih1|Whh1] tf32
static __device__ float g_bias0[Gd];
static __device__ float g_bias1[Gd];
static __device__ __align__(16) float g_h0[2][(size_t)Bsz * Hd];         // h0[b][unit]
static __device__ __align__(16) float g_h1[2][(size_t)Bsz * Hd];         // h1[b][unit]
static __device__ unsigned g_count;

__device__ __forceinline__ float sigf(float x) { return 1.0f / (1.0f + expf(-x)); }

__device__ __forceinline__ float tf32r(float x) {
    uint32_t u;
    asm("cvt.rna.tf32.f32 %0, %1;" : "=r"(u) : "f"(x));
    return __uint_as_float(u);
}

#define FMA4(acc, s, v)                                                        \
    acc.x += (s) * (v).x; acc.y += (s) * (v).y;                                \
    acc.z += (s) * (v).z; acc.w += (s) * (v).w;

#define CP16(dst, src)                                                         \
    asm volatile("cp.async.cg.shared.global [%0], [%1], 16;\n"                 \
                 :: "r"(dst), "l"(src) : "memory")

__device__ __forceinline__ unsigned su32(const void* p) {
    return (unsigned)__cvta_generic_to_shared(p);
}

__device__ __forceinline__ void mma_tf32(float* d,
    uint32_t a0, uint32_t a1, uint32_t a2, uint32_t a3, uint32_t b0, uint32_t b1) {
    asm volatile(
        "mma.sync.aligned.m16n8k8.row.col.f32.tf32.tf32.f32 "
        "{%0,%1,%2,%3}, {%4,%5,%6,%7}, {%8,%9}, {%0,%1,%2,%3};"
        : "+f"(d[0]), "+f"(d[1]), "+f"(d[2]), "+f"(d[3])
        : "r"(a0), "r"(a1), "r"(a2), "r"(a3), "r"(b0), "r"(b1));
}

// ---------------- setup ----------------
__global__ void k_prep(const float* __restrict__ bih0, const float* __restrict__ bhh0,
                       const float* __restrict__ bih1, const float* __restrict__ bhh1,
                       const float* __restrict__ Wih1, const float* __restrict__ Whh1,
                       const float* __restrict__ Whh0) {
    int i = blockIdx.x * blockDim.x + threadIdx.x;
    if (i < Gd * 2 * Hd) {
        int g = i >> 10;
        int k = i & 1023;
        float v = (k < Hd) ? Wih1[(size_t)g * Hd + k] : Whh1[(size_t)g * Hd + (k - Hd)];
        g_Wcat[i] = tf32r(v);
    }
    if (i < Gd * Hd) g_Wh0c[i] = tf32r(Whh0[i]);
    if (i < Gd) { g_bias0[i] = bih0[i] + bhh0[i]; g_bias1[i] = bih1[i] + bhh1[i]; }
    if (i < Bsz * Hd) {
        g_h0[0][i] = 0.0f; g_h0[1][i] = 0.0f;
        g_h1[0][i] = 0.0f; g_h1[1][i] = 0.0f;
    }
    if (i == 0) g_count = 0u;
}

// ---------------- transpose x[b][t][i] -> xT[t][i][b] ----------------
__global__ void k_tr(const float* __restrict__ x) {
    __shared__ float s[32][129];
    int t = blockIdx.x;
    int ic = blockIdx.y * 32;
    int lane = threadIdx.x & 31;
    int wrp  = threadIdx.x >> 5;
    for (int bb = wrp; bb < Bsz; bb += 8)
        s[lane][bb] = x[((size_t)bb * Tlen + t) * Iin + ic + lane];
    __syncthreads();
    for (int r = 0; r < 16; ++r) {
        int idx = threadIdx.x + r * 256;
        int i = idx >> 7, b = idx & 127;
        g_xT[((size_t)t * Iin + ic + i) * Bsz + b] = s[i][b];
    }
}

// ---------------- input GEMM (fp32, exact): xg[t][g][b] ----------------
__global__ void __launch_bounds__(512) k_xgemm(const float* __restrict__ Wih0) {
    int t = blockIdx.y;
    int w = threadIdx.x >> 5, lane = threadIdx.x & 31;
    int g0 = blockIdx.x * 64 + w * 4;
    const float*  wr = Wih0 + (size_t)g0 * Iin;
    const float4* xp = (const float4*)(g_xT + (size_t)t * Iin * Bsz) + lane;
    float b0 = g_bias0[g0 + 0], b1 = g_bias0[g0 + 1];
    float b2 = g_bias0[g0 + 2], b3 = g_bias0[g0 + 3];
    float4 a0 = make_float4(b0, b0, b0, b0);
    float4 a1 = make_float4(b1, b1, b1, b1);
    float4 a2 = make_float4(b2, b2, b2, b2);
    float4 a3 = make_float4(b3, b3, b3, b3);
#pragma unroll 4
    for (int k = 0; k < Iin; k += 4) {
        float4 xa = xp[(k + 0) * 32];
        float4 xb = xp[(k + 1) * 32];
        float4 xc = xp[(k + 2) * 32];
        float4 xd = xp[(k + 3) * 32];
        float4 w0 = *(const float4*)(wr + 0 * Iin + k);
        float4 w1 = *(const float4*)(wr + 1 * Iin + k);
        float4 w2 = *(const float4*)(wr + 2 * Iin + k);
        float4 w3 = *(const float4*)(wr + 3 * Iin + k);
        FMA4(a0, w0.x, xa); FMA4(a0, w0.y, xb); FMA4(a0, w0.z, xc); FMA4(a0, w0.w, xd);
        FMA4(a1, w1.x, xa); FMA4(a1, w1.y, xb); FMA4(a1, w1.z, xc); FMA4(a1, w1.w, xd);
        FMA4(a2, w2.x, xa); FMA4(a2, w2.y, xb); FMA4(a2, w2.z, xc); FMA4(a2, w2.w, xd);
        FMA4(a3, w3.x, xa); FMA4(a3, w3.y, xb); FMA4(a3, w3.z, xc); FMA4(a3, w3.w, xd);
    }
    ((float4*)(g_xg + ((size_t)t * Gd + g0 + 0) * Bsz))[lane] = a0;
    ((float4*)(g_xg + ((size_t)t * Gd + g0 + 1) * Bsz))[lane] = a1;
    ((float4*)(g_xg + ((size_t)t * Gd + g0 + 2) * Bsz))[lane] = a2;
    ((float4*)(g_xg + ((size_t)t * Gd + g0 + 3) * Bsz))[lane] = a3;
}

// ---------------- grid barrier ----------------
__device__ __forceinline__ void gridbar(unsigned expected) {
    __threadfence();
    __syncthreads();
    if (threadIdx.x == 0) {
        atomicAdd(&g_count, 1u);
        while (atomicAdd(&g_count, 0u) < expected) { }
    }
    __syncthreads();
}

// ---------------- persistent tensor-core scan ----------------
// 128 blocks x 256 threads. Block = 16 units (64 gate rows) x 32-batch slice.
// Warp w: gate mg=w&3 (m16 tile = 16 units), batch half nh=w>>2 (n16 = 2 n8 tiles).
// mma.sync.m16n8k8.tf32; weights+h staged via 3-stage cp.async (1 sync/chunk).
__global__ void __launch_bounds__(NT) k_scan(const float* __restrict__ fcw,
                                             const float* __restrict__ fcb,
                                             float* __restrict__ out) {
    extern __shared__ __align__(16) float smem[];
    float* s_w = smem;                               // [3][64][SW]
    float* s_h = smem + 3 * 64 * SW;                 // [3][32][SH]
    float* s_g = smem + 3 * 64 * SW + 3 * 32 * SH;   // [64][SG]

    const int m = threadIdx.x;
    const int w = m >> 5, lane = m & 31;
    const int gq = lane >> 2, tq = lane & 3;         // fragment coords
    const int mg = w & 3, nh = w >> 2;               // warp tile: gate, batch-half
    const int n0 = nh * 16;

    const int ju = blockIdx.x >> 2;
    const int bu = blockIdx.x & 3;
    const int j0 = ju * 16;                          // first unit of this block
    const int b0 = bu * 32;                          // first batch element

    // cp.async duties
    const int dRow = m >> 3;                         // 0..31
    const int seg  = m & 7;                          // 16B segment
    const int wr0  = dRow, wr1 = dRow + 32;          // weight local rows
    const int grow0 = ((wr0 >> 4) << 9) + j0 + (wr0 & 15);
    const int grow1 = ((wr1 >> 4) << 9) + j0 + (wr1 & 15);

    // activation mapping: thread -> (units up, up+8; batch bb)
    const int bb = m >> 3;                           // 0..31
    const int up = m & 7;                            // 0..7

    float c0a = 0.f, c0b = 0.f, c1a = 0.f, c1b = 0.f;
    unsigned bar = 0;
    float acc[2][4];

    // stage one chunk: h tile [32 b][KC k] + weight tile [64 rows][KC k]
    auto issue = [&](int c, const float* wsrc, int K, const float* hA, const float* hB,
                     int csplit) {
        int st = c % 3;
        int kb = c * KC;
        const float* hrow = (c < csplit) ? (hA + kb) : (hB + (kb - csplit * KC));
        CP16(su32(&s_h[st * 32 * SH + dRow * SH + seg * 4]),
             hrow + (size_t)(b0 + dRow) * Hd + seg * 4);
        CP16(su32(&s_w[st * 64 * SW + wr0 * SW + seg * 4]),
             wsrc + (size_t)grow0 * K + kb + seg * 4);
        CP16(su32(&s_w[st * 64 * SW + wr1 * SW + seg * 4]),
             wsrc + (size_t)grow1 * K + kb + seg * 4);
        asm volatile("cp.async.commit_group;\n" ::: "memory");
    };

    auto gemm = [&](const float* wsrc, int K, const float* hA, const float* hB,
                    int csplit) {
        const int NC = K / KC;
        issue(0, wsrc, K, hA, hB, csplit);
        issue(1, wsrc, K, hA, hB, csplit);
        for (int c = 0; c < NC; ++c) {
            if (c < NC - 1) { asm volatile("cp.async.wait_group 1;\n" ::: "memory"); }
            else            { asm volatile("cp.async.wait_group 0;\n" ::: "memory"); }
            __syncthreads();
            if (c + 2 < NC) issue(c + 2, wsrc, K, hA, hB, csplit);
            const uint32_t* ws = (const uint32_t*)(s_w + (c % 3) * 64 * SW);
            const uint32_t* hs = (const uint32_t*)(s_h + (c % 3) * 32 * SH);
#pragma unroll
            for (int ks = 0; ks < KC / 8; ++ks) {
                const int k0 = ks * 8;
                uint32_t a0 = ws[(mg * 16 + gq    ) * SW + k0 + tq    ];
                uint32_t a1 = ws[(mg * 16 + gq + 8) * SW + k0 + tq    ];
                uint32_t a2 = ws[(mg * 16 + gq    ) * SW + k0 + tq + 4];
                uint32_t a3 = ws[(mg * 16 + gq + 8) * SW + k0 + tq + 4];
#pragma unroll
                for (int nt = 0; nt < 2; ++nt) {
                    uint32_t b0r = hs[(n0 + nt * 8 + gq) * SH + k0 + tq    ];
                    uint32_t b1r = hs[(n0 + nt * 8 + gq) * SH + k0 + tq + 4];
                    mma_tf32(acc[nt], a0, a1, a2, a3, b0r, b1r);
                }
            }
        }
        // store D fragments to s_g
#pragma unroll
        for (int nt = 0; nt < 2; ++nt) {
            int col = n0 + nt * 8 + 2 * tq;
            s_g[(mg * 16 + gq    ) * SG + col    ] = acc[nt][0];
            s_g[(mg * 16 + gq    ) * SG + col + 1] = acc[nt][1];
            s_g[(mg * 16 + gq + 8) * SG + col    ] = acc[nt][2];
            s_g[(mg * 16 + gq + 8) * SG + col + 1] = acc[nt][3];
        }
        __syncthreads();
    };

    // ===== prologue A(0): h0(-1)=0 -> gates = xg[0]; write h0(0) -> g_h0[0] =====
    {
        const float* xg0 = g_xg;   // t = 0
        float gi = xg0[((size_t)(0 * Hd) + j0 + up) * Bsz + b0 + bb];
        float gf = xg0[((size_t)(1 * Hd) + j0 + up) * Bsz + b0 + bb];
        float gg = xg0[((size_t)(2 * Hd) + j0 + up) * Bsz + b0 + bb];
        float go = xg0[((size_t)(3 * Hd) + j0 + up) * Bsz + b0 + bb];
        c0a = sigf(gi) * tanhf(gg);
        g_h0[0][(size_t)(b0 + bb) * Hd + j0 + up] = tf32r(sigf(go) * tanhf(c0a));
        gi = xg0[((size_t)(0 * Hd) + j0 + up + 8) * Bsz + b0 + bb];
        gf = xg0[((size_t)(1 * Hd) + j0 + up + 8) * Bsz + b0 + bb];
        gg = xg0[((size_t)(2 * Hd) + j0 + up + 8) * Bsz + b0 + bb];
        go = xg0[((size_t)(3 * Hd) + j0 + up + 8) * Bsz + b0 + bb];
        c0b = sigf(gi) * tanhf(gg);
        g_h0[0][(size_t)(b0 + bb) * Hd + j0 + up + 8] = tf32r(sigf(go) * tanhf(c0b));
        (void)gf;
    }
    gridbar(++bar * NBLK);

    const int r1 = (mg << 9) + j0 + gq;      // global gate row (unit gq)
    const int r2 = r1 + 8;

    for (int t = 0; t < Tlen; ++t) {
        const float* h0cur = g_h0[t & 1];            // h0(t)
        const float* h1prv = g_h1[(t + 1) & 1];      // h1(t-1)
        float*       h1nxt = g_h1[t & 1];            // h1(t)
        float*       h0nxt = g_h0[(t + 1) & 1];      // h0(t+1)

        // ===== B(t): gates = bias1 + Wcat @ [h0(t) | h1(t-1)] -> h1(t) =====
        {
            float bv1 = __ldg(&g_bias1[r1]);
            float bv2 = __ldg(&g_bias1[r2]);
#pragma unroll
            for (int nt = 0; nt < 2; ++nt) {
                acc[nt][0] = bv1; acc[nt][1] = bv1;
                acc[nt][2] = bv2; acc[nt][3] = bv2;
            }
            gemm(g_Wcat, 2 * Hd, h0cur, h1prv, Hd / KC);
            float gi = s_g[(0 * 16 + up) * SG + bb];
            float gf = s_g[(1 * 16 + up) * SG + bb];
            float gg = s_g[(2 * 16 + up) * SG + bb];
            float go = s_g[(3 * 16 + up) * SG + bb];
            c1a = sigf(gf) * c1a + sigf(gi) * tanhf(gg);
            h1nxt[(size_t)(b0 + bb) * Hd + j0 + up] = tf32r(sigf(go) * tanhf(c1a));
            gi = s_g[(0 * 16 + up + 8) * SG + bb];
            gf = s_g[(1 * 16 + up + 8) * SG + bb];
            gg = s_g[(2 * 16 + up + 8) * SG + bb];
            go = s_g[(3 * 16 + up + 8) * SG + bb];
            c1b = sigf(gf) * c1b + sigf(gi) * tanhf(gg);
            h1nxt[(size_t)(b0 + bb) * Hd + j0 + up + 8] = tf32r(sigf(go) * tanhf(c1b));
        }

        // ===== A(t+1): gates = xg[t+1] + Whh0 @ h0(t) -> h0(t+1) =====
        if (t < Tlen - 1) {
            const float* xgt = g_xg + (size_t)(t + 1) * Gd * Bsz;
#pragma unroll
            for (int nt = 0; nt < 2; ++nt) {
                int col = b0 + n0 + nt * 8 + 2 * tq;
                float2 v1 = *(const float2*)(xgt + (size_t)r1 * Bsz + col);
                float2 v2 = *(const float2*)(xgt + (size_t)r2 * Bsz + col);
                acc[nt][0] = v1.x; acc[nt][1] = v1.y;
                acc[nt][2] = v2.x; acc[nt][3] = v2.y;
            }
            gemm(g_Wh0c, Hd, h0cur, h0cur, Hd / KC);
            float gi = s_g[(0 * 16 + up) * SG + bb];
            float gf = s_g[(1 * 16 + up) * SG + bb];
            float gg = s_g[(2 * 16 + up) * SG + bb];
            float go = s_g[(3 * 16 + up) * SG + bb];
            c0a = sigf(gf) * c0a + sigf(gi) * tanhf(gg);
            h0nxt[(size_t)(b0 + bb) * Hd + j0 + up] = tf32r(sigf(go) * tanhf(c0a));
            gi = s_g[(0 * 16 + up + 8) * SG + bb];
            gf = s_g[(1 * 16 + up + 8) * SG + bb];
            gg = s_g[(2 * 16 + up + 8) * SG + bb];
            go = s_g[(3 * 16 + up + 8) * SG + bb];
            c0b = sigf(gf) * c0b + sigf(gi) * tanhf(gg);
            h0nxt[(size_t)(b0 + bb) * Hd + j0 + up + 8] = tf32r(sigf(go) * tanhf(c0b));
        }
        gridbar(++bar * NBLK);
    }

    // ===== final FC (block 0): h1(1023) = g_h1[1023&1] = g_h1[1] =====
    if (blockIdx.x == 0 && m < Bsz) {
        const float* hf = g_h1[1] + (size_t)m * Hd;
        float a = __ldg(fcb);
#pragma unroll 8
        for (int j = 0; j < Hd; ++j)
            a += __ldcg(&hf[j]) * __ldg(&fcw[j]);
        out[m] = a;
    }
}

extern "C" void kernel_launch(void* const* d_in, const int* in_sizes, int n_in,
                              void* d_out, int out_size) {
    const float* x    = (const float*)d_in[0];
    const float* Wih0 = (const float*)d_in[1];
    const float* Whh0 = (const float*)d_in[2];
    const float* bih0 = (const float*)d_in[3];
    const float* bhh0 = (const float*)d_in[4];
    const float* Wih1 = (const float*)d_in[5];
    const float* Whh1 = (const float*)d_in[6];
    const float* bih1 = (const float*)d_in[7];
    const float* bhh1 = (const float*)d_in[8];
    const float* fcw  = (const float*)d_in[9];
    const float* fcb  = (const float*)d_in[10];
    float* out = (float*)d_out;

    cudaFuncSetAttribute(k_scan, cudaFuncAttributeMaxDynamicSharedMemorySize, SMEM_BYTES);

    k_prep<<<(Gd * 2 * Hd) / 256, 256>>>(bih0, bhh0, bih1, bhh1, Wih1, Whh1, Whh0);

    dim3 gtr(Tlen, Iin / 32);
    k_tr<<<gtr, 256>>>(x);

    dim3 gxg(Gd / 64, Tlen);
    k_xgemm<<<gxg, 512>>>(Wih0);

    k_scan<<<NBLK, NT, SMEM_BYTES>>>(fcw, fcb, out);
}

// round 11
// speedup vs baseline: 4.8256x; 1.7836x over previous
#include <cuda_runtime.h>
#include <cuda_fp16.h>
#include <math.h>
#include <stdint.h>

#define Bsz 128
#define Tlen 1024
#define Iin 256
#define Hd 512
#define Gd 2048      // 4*Hd
#define NBLK 128     // 32 unit-groups x 4 batch-slices
#define NT 256
#define KC2 64       // k-chunk (halves) per cp.async stage
#define SW0 520      // s_w0 row stride (halves): 512 + 8 pad (odd*16B)
#define SWC 1032     // s_wc row stride (halves): 1024 + 8 pad
#define SHH 72       // s_h row stride (halves): 64 + 8 pad
#define SGS 33       // s_g row stride (floats)
#define SMEM_BYTES ((64*SW0 + 64*SWC + 3*32*SHH) * 2 + 64*SGS*4)

// ---------------- scratch (static device memory; no allocations) ----------------
static __device__ __align__(16) float  g_xT [(size_t)Tlen * Iin * Bsz];   // [t][i][b]
static __device__ __align__(16) float  g_xg [(size_t)Tlen * Gd  * Bsz];   // [t][g][b]
static __device__ __align__(16) __half g_Wh0h[(size_t)Gd * Hd];           // Whh0 fp16
static __device__ __align__(16) __half g_Wcath[(size_t)Gd * 2 * Hd];      // [Wih1|Whh1] fp16
static __device__ float g_bias0[Gd];
static __device__ float g_bias1[Gd];
static __device__ __align__(16) __half g_h0h[2][(size_t)Bsz * Hd];        // h0[b][unit] fp16
static __device__ __align__(16) __half g_h1h[2][(size_t)Bsz * Hd];        // h1[b][unit] fp16
static __device__ unsigned g_count;

__device__ __forceinline__ float sigf(float x) { return 1.0f / (1.0f + expf(-x)); }

#define FMA4(acc, s, v)                                                        \
    acc.x += (s) * (v).x; acc.y += (s) * (v).y;                                \
    acc.z += (s) * (v).z; acc.w += (s) * (v).w;

#define CP16(dst, src)                                                         \
    asm volatile("cp.async.cg.shared.global [%0], [%1], 16;\n"                 \
                 :: "r"(dst), "l"(src) : "memory")

__device__ __forceinline__ unsigned su32(const void* p) {
    return (unsigned)__cvta_generic_to_shared(p);
}

#define LDSM4(r0, r1, r2, r3, addr)                                            \
    asm volatile("ldmatrix.sync.aligned.m8n8.x4.shared.b16 {%0,%1,%2,%3}, [%4];" \
                 : "=r"(r0), "=r"(r1), "=r"(r2), "=r"(r3) : "r"(addr))

#define MMA168(d, a0, a1, a2, a3, b0, b1)                                      \
    asm volatile("mma.sync.aligned.m16n8k16.row.col.f32.f16.f16.f32 "          \
                 "{%0,%1,%2,%3}, {%4,%5,%6,%7}, {%8,%9}, {%0,%1,%2,%3};"       \
                 : "+f"(d[0]), "+f"(d[1]), "+f"(d[2]), "+f"(d[3])              \
                 : "r"(a0), "r"(a1), "r"(a2), "r"(a3), "r"(b0), "r"(b1))

// ---------------- setup ----------------
__global__ void k_prep(const float* __restrict__ bih0, const float* __restrict__ bhh0,
                       const float* __restrict__ bih1, const float* __restrict__ bhh1,
                       const float* __restrict__ Wih1, const float* __restrict__ Whh1,
                       const float* __restrict__ Whh0) {
    int i = blockIdx.x * blockDim.x + threadIdx.x;
    if (i < Gd * 2 * Hd) {
        int g = i >> 10;
        int k = i & 1023;
        float v = (k < Hd) ? Wih1[(size_t)g * Hd + k] : Whh1[(size_t)g * Hd + (k - Hd)];
        g_Wcath[i] = __float2half(v);
    }
    if (i < Gd * Hd) g_Wh0h[i] = __float2half(Whh0[i]);
    if (i < Gd) { g_bias0[i] = bih0[i] + bhh0[i]; g_bias1[i] = bih1[i] + bhh1[i]; }
    if (i < Bsz * Hd) {
        __half z = __float2half(0.0f);
        g_h0h[0][i] = z; g_h0h[1][i] = z;
        g_h1h[0][i] = z; g_h1h[1][i] = z;
    }
    if (i == 0) g_count = 0u;
}

// ---------------- transpose x[b][t][i] -> xT[t][i][b] ----------------
__global__ void k_tr(const float* __restrict__ x) {
    __shared__ float s[32][129];
    int t = blockIdx.x;
    int ic = blockIdx.y * 32;
    int lane = threadIdx.x & 31;
    int wrp  = threadIdx.x >> 5;
    for (int bb = wrp; bb < Bsz; bb += 8)
        s[lane][bb] = x[((size_t)bb * Tlen + t) * Iin + ic + lane];
    __syncthreads();
    for (int r = 0; r < 16; ++r) {
        int idx = threadIdx.x + r * 256;
        int i = idx >> 7, b = idx & 127;
        g_xT[((size_t)t * Iin + ic + i) * Bsz + b] = s[i][b];
    }
}

// ---------------- input GEMM (fp32, exact): xg[t][g][b] ----------------
__global__ void __launch_bounds__(512) k_xgemm(const float* __restrict__ Wih0) {
    int t = blockIdx.y;
    int w = threadIdx.x >> 5, lane = threadIdx.x & 31;
    int g0 = blockIdx.x * 64 + w * 4;
    const float*  wr = Wih0 + (size_t)g0 * Iin;
    const float4* xp = (const float4*)(g_xT + (size_t)t * Iin * Bsz) + lane;
    float b0 = g_bias0[g0 + 0], b1 = g_bias0[g0 + 1];
    float b2 = g_bias0[g0 + 2], b3 = g_bias0[g0 + 3];
    float4 a0 = make_float4(b0, b0, b0, b0);
    float4 a1 = make_float4(b1, b1, b1, b1);
    float4 a2 = make_float4(b2, b2, b2, b2);
    float4 a3 = make_float4(b3, b3, b3, b3);
#pragma unroll 4
    for (int k = 0; k < Iin; k += 4) {
        float4 xa = xp[(k + 0) * 32];
        float4 xb = xp[(k + 1) * 32];
        float4 xc = xp[(k + 2) * 32];
        float4 xd = xp[(k + 3) * 32];
        float4 w0 = *(const float4*)(wr + 0 * Iin + k);
        float4 w1 = *(const float4*)(wr + 1 * Iin + k);
        float4 w2 = *(const float4*)(wr + 2 * Iin + k);
        float4 w3 = *(const float4*)(wr + 3 * Iin + k);
        FMA4(a0, w0.x, xa); FMA4(a0, w0.y, xb); FMA4(a0, w0.z, xc); FMA4(a0, w0.w, xd);
        FMA4(a1, w1.x, xa); FMA4(a1, w1.y, xb); FMA4(a1, w1.z, xc); FMA4(a1, w1.w, xd);
        FMA4(a2, w2.x, xa); FMA4(a2, w2.y, xb); FMA4(a2, w2.z, xc); FMA4(a2, w2.w, xd);
        FMA4(a3, w3.x, xa); FMA4(a3, w3.y, xb); FMA4(a3, w3.z, xc); FMA4(a3, w3.w, xd);
    }
    ((float4*)(g_xg + ((size_t)t * Gd + g0 + 0) * Bsz))[lane] = a0;
    ((float4*)(g_xg + ((size_t)t * Gd + g0 + 1) * Bsz))[lane] = a1;
    ((float4*)(g_xg + ((size_t)t * Gd + g0 + 2) * Bsz))[lane] = a2;
    ((float4*)(g_xg + ((size_t)t * Gd + g0 + 3) * Bsz))[lane] = a3;
}

// ---------------- grid barrier ----------------
__device__ __forceinline__ void gridbar(unsigned expected) {
    __threadfence();
    __syncthreads();
    if (threadIdx.x == 0) {
        atomicAdd(&g_count, 1u);
        while (atomicAdd(&g_count, 0u) < expected) { }
    }
    __syncthreads();
}

// ---------------- persistent fp16 tensor-core scan, weights resident in smem ----
// 128 blocks x 256 threads. Block = 16 units (64 gate rows) x 32-batch slice.
// Warp w: gate mi=w&3 (m16), batch-half nh=w>>2 (n16).
// mma.m16n8k16.f16 (fp32 accum); h staged via 3-stage cp.async; ldmatrix fragments.
__global__ void __launch_bounds__(NT) k_scan(const float* __restrict__ fcw,
                                             const float* __restrict__ fcb,
                                             float* __restrict__ out) {
    extern __shared__ __align__(16) unsigned char smem_raw[];
    __half* s_w0 = (__half*)smem_raw;                 // [64][SW0]
    __half* s_wc = s_w0 + 64 * SW0;                   // [64][SWC]
    __half* s_h  = s_wc + 64 * SWC;                   // [3][32][SHH]
    float*  s_g  = (float*)(s_h + 3 * 32 * SHH);      // [64][SGS]

    const int m = threadIdx.x;
    const int lane = m & 31, w = m >> 5;
    const int gq = lane >> 2, tq = lane & 3;
    const int mi = w & 3, nh = w >> 2;

    const int ju = blockIdx.x >> 2, bu = blockIdx.x & 3;
    const int j0 = ju * 16, b0 = bu * 32;

    // ldmatrix per-thread addressing (tile tt = lane>>3, row tr = lane&7)
    const int tt = lane >> 3, tr = lane & 7;
    const int aRow = mi * 16 + (tt & 1) * 8 + tr;     // A tiles: (+0k,+0r),(+0k,+8r),(+8k,+0r),(+8k,+8r)
    const int aK   = (tt >> 1) * 8;
    const int bRow = nh * 16 + (tt >> 1) * 8 + tr;    // B tiles: (n+0,k+0),(n+0,k+8),(n+8,k+0),(n+8,k+8)
    const int bK   = (tt & 1) * 8;

    const uint32_t suW0 = su32(s_w0), suWc = su32(s_wc), suH = su32(s_h);
    const uint32_t aBaseW0 = suW0 + (uint32_t)(aRow * SW0 + aK) * 2;
    const uint32_t aBaseWc = suWc + (uint32_t)(aRow * SWC + aK) * 2;
    const uint32_t bBase   = suH  + (uint32_t)(bRow * SHH + bK) * 2;

    // h-stage duties
    const int dRow = m >> 3, seg = m & 7;

    // activation mapping
    const int bb = m >> 3, up = m & 7;

    // ===== load resident weight slices into smem (once) =====
    for (int idx = m; idx < 4096; idx += NT) {          // Whh0: 64 rows x 64 segs
        int r = idx >> 6, sg = idx & 63;
        int grow = ((r >> 4) << 9) + j0 + (r & 15);
        CP16(suW0 + (uint32_t)(r * SW0 + sg * 8) * 2,
             g_Wh0h + (size_t)grow * Hd + sg * 8);
    }
    for (int idx = m; idx < 8192; idx += NT) {          // Wcat: 64 rows x 128 segs
        int r = idx >> 7, sg = idx & 127;
        int grow = ((r >> 4) << 9) + j0 + (r & 15);
        CP16(suWc + (uint32_t)(r * SWC + sg * 8) * 2,
             g_Wcath + (size_t)grow * (2 * Hd) + sg * 8);
    }
    asm volatile("cp.async.commit_group;\n" ::: "memory");
    asm volatile("cp.async.wait_group 0;\n" ::: "memory");
    __syncthreads();

    float c0a = 0.f, c0b = 0.f, c1a = 0.f, c1b = 0.f;
    unsigned bar = 0;
    float acc[2][4];

    auto issue = [&](int c, const __half* hA, const __half* hB, int csplit) {
        int st = c % 3;
        int kb = c * KC2;
        const __half* src = (c < csplit) ? (hA + kb) : (hB + (kb - csplit * KC2));
        CP16(suH + (uint32_t)((st * 32 + dRow) * SHH + seg * 8) * 2,
             src + (size_t)(b0 + dRow) * Hd + seg * 8);
        asm volatile("cp.async.commit_group;\n" ::: "memory");
    };

    auto gemm = [&](uint32_t aBase, int NC, const __half* hA, const __half* hB, int csplit) {
        issue(0, hA, hB, csplit);
        issue(1, hA, hB, csplit);
        for (int c = 0; c < NC; ++c) {
            if (c < NC - 1) { asm volatile("cp.async.wait_group 1;\n" ::: "memory"); }
            else            { asm volatile("cp.async.wait_group 0;\n" ::: "memory"); }
            __syncthreads();
            if (c + 2 < NC) issue(c + 2, hA, hB, csplit);
            uint32_t aA = aBase + (uint32_t)(c * KC2) * 2;
            uint32_t bA = bBase + (uint32_t)((c % 3) * 32 * SHH) * 2;
#pragma unroll
            for (int ks = 0; ks < KC2 / 16; ++ks) {
                uint32_t a0, a1, a2, a3, b0r, b1r, b2r, b3r;
                LDSM4(a0, a1, a2, a3, aA + ks * 32);
                LDSM4(b0r, b1r, b2r, b3r, bA + ks * 32);
                MMA168(acc[0], a0, a1, a2, a3, b0r, b1r);
                MMA168(acc[1], a0, a1, a2, a3, b2r, b3r);
            }
        }
#pragma unroll
        for (int nt = 0; nt < 2; ++nt) {
            int col = nh * 16 + nt * 8 + 2 * tq;
            s_g[(mi * 16 + gq    ) * SGS + col    ] = acc[nt][0];
            s_g[(mi * 16 + gq    ) * SGS + col + 1] = acc[nt][1];
            s_g[(mi * 16 + gq + 8) * SGS + col    ] = acc[nt][2];
            s_g[(mi * 16 + gq + 8) * SGS + col + 1] = acc[nt][3];
        }
        __syncthreads();
    };

    // ===== prologue A(0): h0(-1)=0 -> gates = xg[0]; write h0(0) -> g_h0h[0] =====
    {
        const float* xg0 = g_xg;
        float gi = xg0[((size_t)(0 * Hd) + j0 + up) * Bsz + b0 + bb];
        float gg = xg0[((size_t)(2 * Hd) + j0 + up) * Bsz + b0 + bb];
        float go = xg0[((size_t)(3 * Hd) + j0 + up) * Bsz + b0 + bb];
        c0a = sigf(gi) * tanhf(gg);
        g_h0h[0][(size_t)(b0 + bb) * Hd + j0 + up] = __float2half(sigf(go) * tanhf(c0a));
        gi = xg0[((size_t)(0 * Hd) + j0 + up + 8) * Bsz + b0 + bb];
        gg = xg0[((size_t)(2 * Hd) + j0 + up + 8) * Bsz + b0 + bb];
        go = xg0[((size_t)(3 * Hd) + j0 + up + 8) * Bsz + b0 + bb];
        c0b = sigf(gi) * tanhf(gg);
        g_h0h[0][(size_t)(b0 + bb) * Hd + j0 + up + 8] = __float2half(sigf(go) * tanhf(c0b));
    }
    gridbar(++bar * NBLK);

    const int r1 = (mi << 9) + j0 + gq;      // global gate row for fragment row gq
    const int r2 = r1 + 8;

    for (int t = 0; t < Tlen; ++t) {
        const __half* h0cur = g_h0h[t & 1];
        const __half* h1prv = g_h1h[(t + 1) & 1];
        __half*       h1nxt = g_h1h[t & 1];
        __half*       h0nxt = g_h0h[(t + 1) & 1];

        // ===== B(t): gates = bias1 + Wcat @ [h0(t) | h1(t-1)] -> h1(t) =====
        {
            float bv1 = __ldg(&g_bias1[r1]);
            float bv2 = __ldg(&g_bias1[r2]);
#pragma unroll
            for (int nt = 0; nt < 2; ++nt) {
                acc[nt][0] = bv1; acc[nt][1] = bv1;
                acc[nt][2] = bv2; acc[nt][3] = bv2;
            }
            gemm(aBaseWc, (2 * Hd) / KC2, h0cur, h1prv, Hd / KC2);
            float gi = s_g[(0 * 16 + up) * SGS + bb];
            float gf = s_g[(1 * 16 + up) * SGS + bb];
            float gg = s_g[(2 * 16 + up) * SGS + bb];
            float go = s_g[(3 * 16 + up) * SGS + bb];
            c1a = sigf(gf) * c1a + sigf(gi) * tanhf(gg);
            h1nxt[(size_t)(b0 + bb) * Hd + j0 + up] = __float2half(sigf(go) * tanhf(c1a));
            gi = s_g[(0 * 16 + up + 8) * SGS + bb];
            gf = s_g[(1 * 16 + up + 8) * SGS + bb];
            gg = s_g[(2 * 16 + up + 8) * SGS + bb];
            go = s_g[(3 * 16 + up + 8) * SGS + bb];
            c1b = sigf(gf) * c1b + sigf(gi) * tanhf(gg);
            h1nxt[(size_t)(b0 + bb) * Hd + j0 + up + 8] = __float2half(sigf(go) * tanhf(c1b));
        }

        // ===== A(t+1): gates = xg[t+1] + Whh0 @ h0(t) -> h0(t+1) =====
        if (t < Tlen - 1) {
            const float* xgt = g_xg + (size_t)(t + 1) * Gd * Bsz;
#pragma unroll
            for (int nt = 0; nt < 2; ++nt) {
                int col = b0 + nh * 16 + nt * 8 + 2 * tq;
                float2 v1 = *(const float2*)(xgt + (size_t)r1 * Bsz + col);
                float2 v2 = *(const float2*)(xgt + (size_t)r2 * Bsz + col);
                acc[nt][0] = v1.x; acc[nt][1] = v1.y;
                acc[nt][2] = v2.x; acc[nt][3] = v2.y;
            }
            gemm(aBaseW0, Hd / KC2, h0cur, h0cur, Hd / KC2);
            float gi = s_g[(0 * 16 + up) * SGS + bb];
            float gf = s_g[(1 * 16 + up) * SGS + bb];
            float gg = s_g[(2 * 16 + up) * SGS + bb];
            float go = s_g[(3 * 16 + up) * SGS + bb];
            c0a = sigf(gf) * c0a + sigf(gi) * tanhf(gg);
            h0nxt[(size_t)(b0 + bb) * Hd + j0 + up] = __float2half(sigf(go) * tanhf(c0a));
            gi = s_g[(0 * 16 + up + 8) * SGS + bb];
            gf = s_g[(1 * 16 + up + 8) * SGS + bb];
            gg = s_g[(2 * 16 + up + 8) * SGS + bb];
            go = s_g[(3 * 16 + up + 8) * SGS + bb];
            c0b = sigf(gf) * c0b + sigf(gi) * tanhf(gg);
            h0nxt[(size_t)(b0 + bb) * Hd + j0 + up + 8] = __float2half(sigf(go) * tanhf(c0b));
        }
        gridbar(++bar * NBLK);
    }

    // ===== final FC (block 0): h1(1023) = g_h1h[1023&1] = g_h1h[1] =====
    if (blockIdx.x == 0 && m < Bsz) {
        const __half* hf = g_h1h[1] + (size_t)m * Hd;
        float a = __ldg(fcb);
#pragma unroll 8
        for (int j = 0; j < Hd; ++j)
            a += __half2float(hf[j]) * __ldg(&fcw[j]);
        out[m] = a;
    }
}

extern "C" void kernel_launch(void* const* d_in, const int* in_sizes, int n_in,
                              void* d_out, int out_size) {
    const float* x    = (const float*)d_in[0];
    const float* Wih0 = (const float*)d_in[1];
    const float* Whh0 = (const float*)d_in[2];
    const float* bih0 = (const float*)d_in[3];
    const float* bhh0 = (const float*)d_in[4];
    const float* Wih1 = (const float*)d_in[5];
    const float* Whh1 = (const float*)d_in[6];
    const float* bih1 = (const float*)d_in[7];
    const float* bhh1 = (const float*)d_in[8];
    const float* fcw  = (const float*)d_in[9];
    const float* fcb  = (const float*)d_in[10];
    float* out = (float*)d_out;

    cudaFuncSetAttribute(k_scan, cudaFuncAttributeMaxDynamicSharedMemorySize, SMEM_BYTES);

    k_prep<<<(Gd * 2 * Hd) / 256, 256>>>(bih0, bhh0, bih1, bhh1, Wih1, Whh1, Whh0);

    dim3 gtr(Tlen, Iin / 32);
    k_tr<<<gtr, 256>>>(x);

    dim3 gxg(Gd / 64, Tlen);
    k_xgemm<<<gxg, 512>>>(Wih0);

    k_scan<<<NBLK, NT, SMEM_BYTES>>>(fcw, fcb, out);
}

// round 12
// speedup vs baseline: 7.5238x; 1.5591x over previous
#include <cuda_runtime.h>
#include <cuda_fp16.h>
#include <math.h>
#include <stdint.h>

#define Bsz 128
#define Tlen 1024
#define Iin 256
#define Hd 512
#define Gd 2048      // 4*Hd
#define NBLK 128     // 32 unit-groups x 4 batch-slices
#define NT 256
#define KC2 64       // k-chunk (halves) per cp.async stage (scan)
#define SW0 520      // s_w0 row stride (halves)
#define SWC 1032     // s_wc row stride (halves)
#define SHH 72       // s_h row stride (halves)
#define SGS 33       // s_g row stride (floats)
#define SMEM_SCAN ((64*SW0 + 64*SWC + 3*32*SHH) * 2 + 2*64*SGS*4)
#define SWX 264      // xgemm smem row stride (halves)
#define SMEM_XG ((64*SWX + 2*32*SWX) * 2)

// ---------------- scratch (static device memory; no allocations) ----------------
static __device__ __align__(16) __half g_xh  [(size_t)Bsz * Tlen * Iin];  // x fp16 [b][t][i]
static __device__ __align__(16) float  g_xg [(size_t)Tlen * Gd  * Bsz];   // [t][g][b]
static __device__ __align__(16) __half g_Wih0h[(size_t)Gd * Iin];         // Wih0 fp16
static __device__ __align__(16) __half g_Wh0h[(size_t)Gd * Hd];           // Whh0 fp16
static __device__ __align__(16) __half g_Wcath[(size_t)Gd * 2 * Hd];      // [Wih1|Whh1] fp16
static __device__ float g_bias0[Gd];
static __device__ float g_bias1[Gd];
static __device__ __align__(16) __half g_h0h[2][(size_t)Bsz * Hd];        // h0[b][unit] fp16
static __device__ __align__(16) __half g_h1h[2][(size_t)Bsz * Hd];        // h1[b][unit] fp16
static __device__ volatile unsigned g_count;

__device__ __forceinline__ float sigf(float x) { return 1.0f / (1.0f + expf(-x)); }

#define CP16(dst, src)                                                         \
    asm volatile("cp.async.cg.shared.global [%0], [%1], 16;\n"                 \
                 :: "r"(dst), "l"(src) : "memory")

__device__ __forceinline__ unsigned su32(const void* p) {
    return (unsigned)__cvta_generic_to_shared(p);
}

#define LDSM4(r0, r1, r2, r3, addr)                                            \
    asm volatile("ldmatrix.sync.aligned.m8n8.x4.shared.b16 {%0,%1,%2,%3}, [%4];" \
                 : "=r"(r0), "=r"(r1), "=r"(r2), "=r"(r3) : "r"(addr))

#define MMA168(d, a0, a1, a2, a3, b0, b1)                                      \
    asm volatile("mma.sync.aligned.m16n8k16.row.col.f32.f16.f16.f32 "          \
                 "{%0,%1,%2,%3}, {%4,%5,%6,%7}, {%8,%9}, {%0,%1,%2,%3};"       \
                 : "+f"(d[0]), "+f"(d[1]), "+f"(d[2]), "+f"(d[3])              \
                 : "r"(a0), "r"(a1), "r"(a2), "r"(a3), "r"(b0), "r"(b1))

// ---------------- setup ----------------
__global__ void k_prep(const float* __restrict__ bih0, const float* __restrict__ bhh0,
                       const float* __restrict__ bih1, const float* __restrict__ bhh1,
                       const float* __restrict__ Wih1, const float* __restrict__ Whh1,
                       const float* __restrict__ Whh0, const float* __restrict__ Wih0) {
    int i = blockIdx.x * blockDim.x + threadIdx.x;
    if (i < Gd * 2 * Hd) {
        int g = i >> 10;
        int k = i & 1023;
        float v = (k < Hd) ? Wih1[(size_t)g * Hd + k] : Whh1[(size_t)g * Hd + (k - Hd)];
        g_Wcath[i] = __float2half(v);
    }
    if (i < Gd * Hd) g_Wh0h[i] = __float2half(Whh0[i]);
    if (i < Gd * Iin) g_Wih0h[i] = __float2half(Wih0[i]);
    if (i < Gd) { g_bias0[i] = bih0[i] + bhh0[i]; g_bias1[i] = bih1[i] + bhh1[i]; }
    if (i < Bsz * Hd) {
        __half z = __float2half(0.0f);
        g_h0h[0][i] = z; g_h0h[1][i] = z;
        g_h1h[0][i] = z; g_h1h[1][i] = z;
    }
    if (i == 0) g_count = 0u;
}

// ---------------- x -> fp16 ----------------
__global__ void k_xh(const float* __restrict__ x) {
    size_t gid = (size_t)blockIdx.x * blockDim.x + threadIdx.x;
    const float4* src = (const float4*)x + gid * 2;
    float4 v0 = src[0], v1 = src[1];
    __half2 h0 = __floats2half2_rn(v0.x, v0.y);
    __half2 h1 = __floats2half2_rn(v0.z, v0.w);
    __half2 h2 = __floats2half2_rn(v1.x, v1.y);
    __half2 h3 = __floats2half2_rn(v1.z, v1.w);
    uint4 u;
    u.x = *(unsigned*)&h0; u.y = *(unsigned*)&h1;
    u.z = *(unsigned*)&h2; u.w = *(unsigned*)&h3;
    ((uint4*)g_xh)[gid] = u;
}

// ---------------- input GEMM (fp16 tensor cores): xg[t][g][b] = W@x + bias0 ----
// 128 blocks (32 unit-groups x 4 batch-slices), 256 thr. W slice resident; loop t.
__global__ void __launch_bounds__(NT) k_xgemm() {
    extern __shared__ __align__(16) unsigned char smem_raw[];
    __half* s_w = (__half*)smem_raw;             // [64][SWX]
    __half* s_x = s_w + 64 * SWX;                // [2][32][SWX]

    const int m = threadIdx.x;
    const int lane = m & 31, w = m >> 5;
    const int gq = lane >> 2, tq = lane & 3;
    const int mi = w & 3, nh = w >> 2;
    const int tt = lane >> 3, tr = lane & 7;

    const int ju = blockIdx.x >> 2, bu = blockIdx.x & 3;
    const int j0 = ju * 16, b0 = bu * 32;

    const int aRow = mi * 16 + (tt & 1) * 8 + tr;
    const int aK   = (tt >> 1) * 8;
    const int bRow = nh * 16 + (tt >> 1) * 8 + tr;
    const int bK   = (tt & 1) * 8;

    const uint32_t suW = su32(s_w), suX = su32(s_x);
    const uint32_t aBase = suW + (uint32_t)(aRow * SWX + aK) * 2;
    const uint32_t bBase = suX + (uint32_t)(bRow * SWX + bK) * 2;

    const int xRow = m >> 3;                     // staging duties
    const int xSeg = m & 7;

    // resident W slice: 64 rows x 32 segs
    for (int idx = m; idx < 2048; idx += NT) {
        int r = idx >> 5, sg = idx & 31;
        int grow = ((r >> 4) << 9) + j0 + (r & 15);
        CP16(suW + (uint32_t)(r * SWX + sg * 8) * 2,
             g_Wih0h + (size_t)grow * Iin + sg * 8);
    }
    asm volatile("cp.async.commit_group;\n" ::: "memory");

    auto issueX = [&](int t) {
        int buf = t & 1;
#pragma unroll
        for (int ss = 0; ss < 4; ++ss) {
            int seg = xSeg + ss * 8;
            CP16(suX + (uint32_t)((buf * 32 + xRow) * SWX + seg * 8) * 2,
                 g_xh + ((size_t)(b0 + xRow) * Tlen + t) * Iin + seg * 8);
        }
        asm volatile("cp.async.commit_group;\n" ::: "memory");
    };
    issueX(0);

    const int r1 = (mi << 9) + j0 + gq;
    const int r2 = r1 + 8;
    const float bv1 = g_bias0[r1];
    const float bv2 = g_bias0[r2];

    for (int t = 0; t < Tlen; ++t) {
        asm volatile("cp.async.wait_group 0;\n" ::: "memory");
        __syncthreads();
        if (t + 1 < Tlen) issueX(t + 1);

        float acc[2][4];
#pragma unroll
        for (int nt = 0; nt < 2; ++nt) {
            acc[nt][0] = bv1; acc[nt][1] = bv1;
            acc[nt][2] = bv2; acc[nt][3] = bv2;
        }
        const uint32_t bA = bBase + (uint32_t)((t & 1) * 32 * SWX) * 2;
#pragma unroll
        for (int ks = 0; ks < Iin / 16; ++ks) {
            uint32_t a0, a1, a2, a3, b0r, b1r, b2r, b3r;
            LDSM4(a0, a1, a2, a3, aBase + ks * 32);
            LDSM4(b0r, b1r, b2r, b3r, bA + ks * 32);
            MMA168(acc[0], a0, a1, a2, a3, b0r, b1r);
            MMA168(acc[1], a0, a1, a2, a3, b2r, b3r);
        }
        float* xgt = g_xg + (size_t)t * Gd * Bsz;
#pragma unroll
        for (int nt = 0; nt < 2; ++nt) {
            int col = b0 + nh * 16 + nt * 8 + 2 * tq;
            *(float2*)(xgt + (size_t)r1 * Bsz + col) = make_float2(acc[nt][0], acc[nt][1]);
            *(float2*)(xgt + (size_t)r2 * Bsz + col) = make_float2(acc[nt][2], acc[nt][3]);
        }
        __syncthreads();
    }
}

// ---------------- grid barrier (volatile-poll spin) ----------------
__device__ __forceinline__ void gridbar(unsigned expected) {
    __threadfence();
    __syncthreads();
    if (threadIdx.x == 0) {
        atomicAdd((unsigned*)&g_count, 1u);
        while (g_count < expected) { }
    }
    __syncthreads();
}

// ---------------- persistent fp16 tensor-core scan, fused dual-GEMM ------------
// 128 blocks x 256 threads. Block = 16 units (64 gate rows) x 32-batch slice.
// Per step one fused chunk loop: chunks 0..7 stage h0(t) and feed BOTH Whh0 (accA,
// layer0 t+1) and Wcat[:, :512] (accB); chunks 8..15 stage h1(t-1) for Wcat[:,512:].
// One grid barrier per step.
__global__ void __launch_bounds__(NT) k_scan(const float* __restrict__ fcw,
                                             const float* __restrict__ fcb,
                                             float* __restrict__ out) {
    extern __shared__ __align__(16) unsigned char smem_raw[];
    __half* s_w0 = (__half*)smem_raw;                 // [64][SW0]
    __half* s_wc = s_w0 + 64 * SW0;                   // [64][SWC]
    __half* s_h  = s_wc + 64 * SWC;                   // [3][32][SHH]
    float*  s_gA = (float*)(s_h + 3 * 32 * SHH);      // [64][SGS]
    float*  s_gB = s_gA + 64 * SGS;                   // [64][SGS]

    const int m = threadIdx.x;
    const int lane = m & 31, w = m >> 5;
    const int gq = lane >> 2, tq = lane & 3;
    const int mi = w & 3, nh = w >> 2;
    const int tt = lane >> 3, tr = lane & 7;

    const int ju = blockIdx.x >> 2, bu = blockIdx.x & 3;
    const int j0 = ju * 16, b0 = bu * 32;

    const int aRow = mi * 16 + (tt & 1) * 8 + tr;
    const int aK   = (tt >> 1) * 8;
    const int bRow = nh * 16 + (tt >> 1) * 8 + tr;
    const int bK   = (tt & 1) * 8;

    const uint32_t suW0 = su32(s_w0), suWc = su32(s_wc), suH = su32(s_h);
    const uint32_t aBaseW0 = suW0 + (uint32_t)(aRow * SW0 + aK) * 2;
    const uint32_t aBaseWc = suWc + (uint32_t)(aRow * SWC + aK) * 2;
    const uint32_t bBase   = suH  + (uint32_t)(bRow * SHH + bK) * 2;

    const int dRow = m >> 3, seg = m & 7;            // h-stage duties
    const int bb = m >> 3, up = m & 7;               // activation mapping

    // ===== resident weight slices =====
    for (int idx = m; idx < 4096; idx += NT) {
        int r = idx >> 6, sg = idx & 63;
        int grow = ((r >> 4) << 9) + j0 + (r & 15);
        CP16(suW0 + (uint32_t)(r * SW0 + sg * 8) * 2,
             g_Wh0h + (size_t)grow * Hd + sg * 8);
    }
    for (int idx = m; idx < 8192; idx += NT) {
        int r = idx >> 7, sg = idx & 127;
        int grow = ((r >> 4) << 9) + j0 + (r & 15);
        CP16(suWc + (uint32_t)(r * SWC + sg * 8) * 2,
             g_Wcath + (size_t)grow * (2 * Hd) + sg * 8);
    }
    asm volatile("cp.async.commit_group;\n" ::: "memory");
    asm volatile("cp.async.wait_group 0;\n" ::: "memory");
    __syncthreads();

    float c0a = 0.f, c0b = 0.f, c1a = 0.f, c1b = 0.f;
    unsigned bar = 0;

    // ===== prologue A(0): h0(-1)=0 -> gates = xg[0]; write h0(0) -> g_h0h[0] =====
    {
        const float* xg0 = g_xg;
        float gi = xg0[((size_t)(0 * Hd) + j0 + up) * Bsz + b0 + bb];
        float gg = xg0[((size_t)(2 * Hd) + j0 + up) * Bsz + b0 + bb];
        float go = xg0[((size_t)(3 * Hd) + j0 + up) * Bsz + b0 + bb];
        c0a = sigf(gi) * tanhf(gg);
        g_h0h[0][(size_t)(b0 + bb) * Hd + j0 + up] = __float2half(sigf(go) * tanhf(c0a));
        gi = xg0[((size_t)(0 * Hd) + j0 + up + 8) * Bsz + b0 + bb];
        gg = xg0[((size_t)(2 * Hd) + j0 + up + 8) * Bsz + b0 + bb];
        go = xg0[((size_t)(3 * Hd) + j0 + up + 8) * Bsz + b0 + bb];
        c0b = sigf(gi) * tanhf(gg);
        g_h0h[0][(size_t)(b0 + bb) * Hd + j0 + up + 8] = __float2half(sigf(go) * tanhf(c0b));
    }
    gridbar(++bar * NBLK);

    const int r1 = (mi << 9) + j0 + gq;
    const int r2 = r1 + 8;
    const float bv1 = __ldg(&g_bias1[r1]);
    const float bv2 = __ldg(&g_bias1[r2]);

    for (int t = 0; t < Tlen; ++t) {
        const __half* h0cur = g_h0h[t & 1];          // h0(t)
        const __half* h1prv = g_h1h[(t + 1) & 1];    // h1(t-1)
        __half*       h1nxt = g_h1h[t & 1];          // h1(t)
        __half*       h0nxt = g_h0h[(t + 1) & 1];    // h0(t+1)
        const int tA = (t + 1 < Tlen) ? (t + 1) : t; // clamped for accA init

        float accA[2][4], accB[2][4];
        // accB init: bias1; accA init: xg[tA] fragments
#pragma unroll
        for (int nt = 0; nt < 2; ++nt) {
            accB[nt][0] = bv1; accB[nt][1] = bv1;
            accB[nt][2] = bv2; accB[nt][3] = bv2;
        }
        {
            const float* xgt = g_xg + (size_t)tA * Gd * Bsz;
#pragma unroll
            for (int nt = 0; nt < 2; ++nt) {
                int col = b0 + nh * 16 + nt * 8 + 2 * tq;
                float2 v1 = *(const float2*)(xgt + (size_t)r1 * Bsz + col);
                float2 v2 = *(const float2*)(xgt + (size_t)r2 * Bsz + col);
                accA[nt][0] = v1.x; accA[nt][1] = v1.y;
                accA[nt][2] = v2.x; accA[nt][3] = v2.y;
            }
        }

        auto issue = [&](int c) {
            int st = c % 3;
            const __half* src = (c < 8) ? (h0cur + c * KC2) : (h1prv + (c - 8) * KC2);
            CP16(suH + (uint32_t)((st * 32 + dRow) * SHH + seg * 8) * 2,
                 src + (size_t)(b0 + dRow) * Hd + seg * 8);
            asm volatile("cp.async.commit_group;\n" ::: "memory");
        };

        issue(0); issue(1);
#pragma unroll 1
        for (int c = 0; c < 16; ++c) {
            if (c < 15) { asm volatile("cp.async.wait_group 1;\n" ::: "memory"); }
            else        { asm volatile("cp.async.wait_group 0;\n" ::: "memory"); }
            __syncthreads();
            if (c + 2 < 16) issue(c + 2);
            const uint32_t bA = bBase + (uint32_t)((c % 3) * 32 * SHH) * 2;
            if (c < 8) {
#pragma unroll
                for (int ks = 0; ks < KC2 / 16; ++ks) {
                    uint32_t a0, a1, a2, a3, e0, e1, e2, e3, b0r, b1r, b2r, b3r;
                    LDSM4(b0r, b1r, b2r, b3r, bA + ks * 32);
                    LDSM4(a0, a1, a2, a3, aBaseW0 + c * 128 + ks * 32);
                    LDSM4(e0, e1, e2, e3, aBaseWc + c * 128 + ks * 32);
                    MMA168(accA[0], a0, a1, a2, a3, b0r, b1r);
                    MMA168(accA[1], a0, a1, a2, a3, b2r, b3r);
                    MMA168(accB[0], e0, e1, e2, e3, b0r, b1r);
                    MMA168(accB[1], e0, e1, e2, e3, b2r, b3r);
                }
            } else {
#pragma unroll
                for (int ks = 0; ks < KC2 / 16; ++ks) {
                    uint32_t e0, e1, e2, e3, b0r, b1r, b2r, b3r;
                    LDSM4(b0r, b1r, b2r, b3r, bA + ks * 32);
                    LDSM4(e0, e1, e2, e3, aBaseWc + c * 128 + ks * 32);
                    MMA168(accB[0], e0, e1, e2, e3, b0r, b1r);
                    MMA168(accB[1], e0, e1, e2, e3, b2r, b3r);
                }
            }
        }

        // publish both gate sets
#pragma unroll
        for (int nt = 0; nt < 2; ++nt) {
            int col = nh * 16 + nt * 8 + 2 * tq;
            s_gA[(mi * 16 + gq    ) * SGS + col    ] = accA[nt][0];
            s_gA[(mi * 16 + gq    ) * SGS + col + 1] = accA[nt][1];
            s_gA[(mi * 16 + gq + 8) * SGS + col    ] = accA[nt][2];
            s_gA[(mi * 16 + gq + 8) * SGS + col + 1] = accA[nt][3];
            s_gB[(mi * 16 + gq    ) * SGS + col    ] = accB[nt][0];
            s_gB[(mi * 16 + gq    ) * SGS + col + 1] = accB[nt][1];
            s_gB[(mi * 16 + gq + 8) * SGS + col    ] = accB[nt][2];
            s_gB[(mi * 16 + gq + 8) * SGS + col + 1] = accB[nt][3];
        }
        __syncthreads();

        // ===== activation B(t) -> h1(t) =====
        {
            float gi = s_gB[(0 * 16 + up) * SGS + bb];
            float gf = s_gB[(1 * 16 + up) * SGS + bb];
            float gg = s_gB[(2 * 16 + up) * SGS + bb];
            float go = s_gB[(3 * 16 + up) * SGS + bb];
            c1a = sigf(gf) * c1a + sigf(gi) * tanhf(gg);
            h1nxt[(size_t)(b0 + bb) * Hd + j0 + up] = __float2half(sigf(go) * tanhf(c1a));
            gi = s_gB[(0 * 16 + up + 8) * SGS + bb];
            gf = s_gB[(1 * 16 + up + 8) * SGS + bb];
            gg = s_gB[(2 * 16 + up + 8) * SGS + bb];
            go = s_gB[(3 * 16 + up + 8) * SGS + bb];
            c1b = sigf(gf) * c1b + sigf(gi) * tanhf(gg);
            h1nxt[(size_t)(b0 + bb) * Hd + j0 + up + 8] = __float2half(sigf(go) * tanhf(c1b));
        }
        // ===== activation A(t+1) -> h0(t+1) (bogus-but-unused at t=1023) =====
        {
            float gi = s_gA[(0 * 16 + up) * SGS + bb];
            float gf = s_gA[(1 * 16 + up) * SGS + bb];
            float gg = s_gA[(2 * 16 + up) * SGS + bb];
            float go = s_gA[(3 * 16 + up) * SGS + bb];
            c0a = sigf(gf) * c0a + sigf(gi) * tanhf(gg);
            h0nxt[(size_t)(b0 + bb) * Hd + j0 + up] = __float2half(sigf(go) * tanhf(c0a));
            gi = s_gA[(0 * 16 + up + 8) * SGS + bb];
            gf = s_gA[(1 * 16 + up + 8) * SGS + bb];
            gg = s_gA[(2 * 16 + up + 8) * SGS + bb];
            go = s_gA[(3 * 16 + up + 8) * SGS + bb];
            c0b = sigf(gf) * c0b + sigf(gi) * tanhf(gg);
            h0nxt[(size_t)(b0 + bb) * Hd + j0 + up + 8] = __float2half(sigf(go) * tanhf(c0b));
        }
        gridbar(++bar * NBLK);
    }

    // ===== final FC (block 0): h1(1023) = g_h1h[1] =====
    if (blockIdx.x == 0 && m < Bsz) {
        const __half* hf = g_h1h[1] + (size_t)m * Hd;
        float a = __ldg(fcb);
#pragma unroll 8
        for (int j = 0; j < Hd; ++j)
            a += __half2float(hf[j]) * __ldg(&fcw[j]);
        out[m] = a;
    }
}

extern "C" void kernel_launch(void* const* d_in, const int* in_sizes, int n_in,
                              void* d_out, int out_size) {
    const float* x    = (const float*)d_in[0];
    const float* Wih0 = (const float*)d_in[1];
    const float* Whh0 = (const float*)d_in[2];
    const float* bih0 = (const float*)d_in[3];
    const float* bhh0 = (const float*)d_in[4];
    const float* Wih1 = (const float*)d_in[5];
    const float* Whh1 = (const float*)d_in[6];
    const float* bih1 = (const float*)d_in[7];
    const float* bhh1 = (const float*)d_in[8];
    const float* fcw  = (const float*)d_in[9];
    const float* fcb  = (const float*)d_in[10];
    float* out = (float*)d_out;

    cudaFuncSetAttribute(k_scan, cudaFuncAttributeMaxDynamicSharedMemorySize, SMEM_SCAN);
    cudaFuncSetAttribute(k_xgemm, cudaFuncAttributeMaxDynamicSharedMemorySize, SMEM_XG);

    k_prep<<<(Gd * 2 * Hd) / 256, 256>>>(bih0, bhh0, bih1, bhh1, Wih1, Whh1, Whh0, Wih0);

    k_xh<<<((size_t)Bsz * Tlen * Iin / 8) / 256, 256>>>(x);

    k_xgemm<<<NBLK, NT, SMEM_XG>>>();

    k_scan<<<NBLK, NT, SMEM_SCAN>>>(fcw, fcb, out);
}

// round 13
// speedup vs baseline: 7.9150x; 1.0520x over previous
#include <cuda_runtime.h>
#include <cuda_fp16.h>
#include <math.h>
#include <stdint.h>

#define Bsz 128
#define Tlen 1024
#define Iin 256
#define Hd 512
#define Gd 2048      // 4*Hd
#define NBLK 128     // 32 unit-groups x 4 batch-slices
#define NT 256
#define SW0 520      // s_w0 row stride (halves)
#define SWC 1032     // s_wc row stride (halves)
#define SHH 136      // h stage row stride (halves): 128 + 8 pad (17*16B)
#define SMEM_SCAN ((64*SW0 + 64*SWC + 3*32*SHH) * 2)
#define SWX 264      // xgemm smem row stride (halves)
#define SMEM_XG ((64*SWX + 2*32*SWX) * 2)

// ---------------- scratch (static device memory; no allocations) ----------------
static __device__ __align__(16) __half g_xh  [(size_t)Bsz * Tlen * Iin];  // x fp16 [b][t][i]
static __device__ __align__(16) float  g_xg [(size_t)Tlen * Gd  * Bsz];   // [t][g][b]
static __device__ __align__(16) __half g_Wih0h[(size_t)Gd * Iin];         // Wih0 fp16
static __device__ __align__(16) __half g_Wh0h[(size_t)Gd * Hd];           // Whh0 fp16
static __device__ __align__(16) __half g_Wcath[(size_t)Gd * 2 * Hd];      // [Wih1|Whh1] fp16
static __device__ float g_bias0[Gd];
static __device__ float g_bias1[Gd];
static __device__ __align__(16) __half g_h0h[2][(size_t)Bsz * Hd];        // h0[b][unit] fp16
static __device__ __align__(16) __half g_h1h[2][(size_t)Bsz * Hd];        // h1[b][unit] fp16
static __device__ volatile unsigned g_cnt[4 * 32];   // per-slice barrier counters (128B apart)

__device__ __forceinline__ float sigf(float x) { return 1.0f / (1.0f + expf(-x)); }

#define CP16(dst, src)                                                         \
    asm volatile("cp.async.cg.shared.global [%0], [%1], 16;\n"                 \
                 :: "r"(dst), "l"(src) : "memory")

__device__ __forceinline__ unsigned su32(const void* p) {
    return (unsigned)__cvta_generic_to_shared(p);
}

#define LDSM4(r0, r1, r2, r3, addr)                                            \
    asm volatile("ldmatrix.sync.aligned.m8n8.x4.shared.b16 {%0,%1,%2,%3}, [%4];" \
                 : "=r"(r0), "=r"(r1), "=r"(r2), "=r"(r3) : "r"(addr))

#define MMA168(d, a0, a1, a2, a3, b0, b1)                                      \
    asm volatile("mma.sync.aligned.m16n8k16.row.col.f32.f16.f16.f32 "          \
                 "{%0,%1,%2,%3}, {%4,%5,%6,%7}, {%8,%9}, {%0,%1,%2,%3};"       \
                 : "+f"(d[0]), "+f"(d[1]), "+f"(d[2]), "+f"(d[3])              \
                 : "r"(a0), "r"(a1), "r"(a2), "r"(a3), "r"(b0), "r"(b1))

// ---------------- setup ----------------
__global__ void k_prep(const float* __restrict__ bih0, const float* __restrict__ bhh0,
                       const float* __restrict__ bih1, const float* __restrict__ bhh1,
                       const float* __restrict__ Wih1, const float* __restrict__ Whh1,
                       const float* __restrict__ Whh0, const float* __restrict__ Wih0) {
    int i = blockIdx.x * blockDim.x + threadIdx.x;
    if (i < Gd * 2 * Hd) {
        int g = i >> 10;
        int k = i & 1023;
        float v = (k < Hd) ? Wih1[(size_t)g * Hd + k] : Whh1[(size_t)g * Hd + (k - Hd)];
        g_Wcath[i] = __float2half(v);
    }
    if (i < Gd * Hd) g_Wh0h[i] = __float2half(Whh0[i]);
    if (i < Gd * Iin) g_Wih0h[i] = __float2half(Wih0[i]);
    if (i < Gd) { g_bias0[i] = bih0[i] + bhh0[i]; g_bias1[i] = bih1[i] + bhh1[i]; }
    if (i < Bsz * Hd) {
        __half z = __float2half(0.0f);
        g_h0h[0][i] = z; g_h0h[1][i] = z;
        g_h1h[0][i] = z; g_h1h[1][i] = z;
    }
    if (i < 4 * 32) g_cnt[i] = 0u;
}

// ---------------- x -> fp16 ----------------
__global__ void k_xh(const float* __restrict__ x) {
    size_t gid = (size_t)blockIdx.x * blockDim.x + threadIdx.x;
    const float4* src = (const float4*)x + gid * 2;
    float4 v0 = src[0], v1 = src[1];
    __half2 h0 = __floats2half2_rn(v0.x, v0.y);
    __half2 h1 = __floats2half2_rn(v0.z, v0.w);
    __half2 h2 = __floats2half2_rn(v1.x, v1.y);
    __half2 h3 = __floats2half2_rn(v1.z, v1.w);
    uint4 u;
    u.x = *(unsigned*)&h0; u.y = *(unsigned*)&h1;
    u.z = *(unsigned*)&h2; u.w = *(unsigned*)&h3;
    ((uint4*)g_xh)[gid] = u;
}

// ---------------- input GEMM (fp16 tensor cores): xg[t][g][b] = W@x + bias0 ----
__global__ void __launch_bounds__(NT) k_xgemm() {
    extern __shared__ __align__(16) unsigned char smem_raw[];
    __half* s_w = (__half*)smem_raw;             // [64][SWX]
    __half* s_x = s_w + 64 * SWX;                // [2][32][SWX]

    const int m = threadIdx.x;
    const int lane = m & 31, w = m >> 5;
    const int gq = lane >> 2, tq = lane & 3;
    const int mi = w & 3, nh = w >> 2;
    const int tt = lane >> 3, tr = lane & 7;

    const int ju = blockIdx.x >> 2, bu = blockIdx.x & 3;
    const int j0 = ju * 16, b0 = bu * 32;

    const int aRow = mi * 16 + (tt & 1) * 8 + tr;
    const int aK   = (tt >> 1) * 8;
    const int bRow = nh * 16 + (tt >> 1) * 8 + tr;
    const int bK   = (tt & 1) * 8;

    const uint32_t suW = su32(s_w), suX = su32(s_x);
    const uint32_t aBase = suW + (uint32_t)(aRow * SWX + aK) * 2;
    const uint32_t bBase = suX + (uint32_t)(bRow * SWX + bK) * 2;

    const int xRow = m >> 3;
    const int xSeg = m & 7;

    for (int idx = m; idx < 2048; idx += NT) {
        int r = idx >> 5, sg = idx & 31;
        int grow = ((r >> 4) << 9) + j0 + (r & 15);
        CP16(suW + (uint32_t)(r * SWX + sg * 8) * 2,
             g_Wih0h + (size_t)grow * Iin + sg * 8);
    }
    asm volatile("cp.async.commit_group;\n" ::: "memory");

    auto issueX = [&](int t) {
        int buf = t & 1;
#pragma unroll
        for (int ss = 0; ss < 4; ++ss) {
            int seg = xSeg + ss * 8;
            CP16(suX + (uint32_t)((buf * 32 + xRow) * SWX + seg * 8) * 2,
                 g_xh + ((size_t)(b0 + xRow) * Tlen + t) * Iin + seg * 8);
        }
        asm volatile("cp.async.commit_group;\n" ::: "memory");
    };
    issueX(0);

    const int r1 = (mi << 9) + j0 + gq;
    const int r2 = r1 + 8;
    const float bv1 = g_bias0[r1];
    const float bv2 = g_bias0[r2];

    for (int t = 0; t < Tlen; ++t) {
        asm volatile("cp.async.wait_group 0;\n" ::: "memory");
        __syncthreads();
        if (t + 1 < Tlen) issueX(t + 1);

        float acc[2][4];
#pragma unroll
        for (int nt = 0; nt < 2; ++nt) {
            acc[nt][0] = bv1; acc[nt][1] = bv1;
            acc[nt][2] = bv2; acc[nt][3] = bv2;
        }
        const uint32_t bA = bBase + (uint32_t)((t & 1) * 32 * SWX) * 2;
#pragma unroll
        for (int ks = 0; ks < Iin / 16; ++ks) {
            uint32_t a0, a1, a2, a3, b0r, b1r, b2r, b3r;
            LDSM4(a0, a1, a2, a3, aBase + ks * 32);
            LDSM4(b0r, b1r, b2r, b3r, bA + ks * 32);
            MMA168(acc[0], a0, a1, a2, a3, b0r, b1r);
            MMA168(acc[1], a0, a1, a2, a3, b2r, b3r);
        }
        float* xgt = g_xg + (size_t)t * Gd * Bsz;
#pragma unroll
        for (int nt = 0; nt < 2; ++nt) {
            int col = b0 + nh * 16 + nt * 8 + 2 * tq;
            *(float2*)(xgt + (size_t)r1 * Bsz + col) = make_float2(acc[nt][0], acc[nt][1]);
            *(float2*)(xgt + (size_t)r2 * Bsz + col) = make_float2(acc[nt][2], acc[nt][3]);
        }
        __syncthreads();
    }
}

// ---------------- per-slice grid barrier (32 blocks each) ----------------
__device__ __forceinline__ void gridbar(int bu, unsigned expected) {
    __threadfence();
    __syncthreads();
    if (threadIdx.x == 0) {
        atomicAdd((unsigned*)&g_cnt[bu * 32], 1u);
        while (g_cnt[bu * 32] < expected) { }
    }
    __syncthreads();
}

// ---------------- persistent fp16 tensor-core scan, m32n16 role-split warps ----
// 128 blocks x 256 threads. Block = 16 units (64 gate rows per matrix) x 32 batch.
// Warps 0-3: Whh0 (k=512, chunks 0-3). Warps 4-7: Wcat (k=1024, chunks 0-7).
// Warp tile m32n16 -> each output row owned by exactly one warp. KC=128 halves,
// 3-stage cp.async h pipeline; gate exchange aliased into dead stages 0 & 2.
__global__ void __launch_bounds__(NT) k_scan(const float* __restrict__ fcw,
                                             const float* __restrict__ fcb,
                                             float* __restrict__ out) {
    extern __shared__ __align__(16) unsigned char smem_raw[];
    __half* s_w0 = (__half*)smem_raw;                 // [64][SW0]
    __half* s_wc = s_w0 + 64 * SW0;                   // [64][SWC]
    __half* s_h  = s_wc + 64 * SWC;                   // [3][32][SHH]
    float*  s_gA = (float*)s_h;                       // union: stage 0 (64x32 sw)
    float*  s_gB = (float*)(s_h + 2 * 32 * SHH);      // union: stage 2 (64x32 sw)

    const int m = threadIdx.x;
    const int lane = m & 31, w = m >> 5;
    const int gq = lane >> 2, tq = lane & 3;
    const int tt = lane >> 3, tr = lane & 7;

    const bool isW0 = (w < 4);
    const int sub = isW0 ? w : (w - 4);
    const int rb = sub >> 1;                          // row block (rows rb*32..+31)
    const int nh = sub & 1;                           // batch half

    const int ju = blockIdx.x >> 2, bu = blockIdx.x & 3;
    const int j0 = ju * 16, b0 = bu * 32;

    // A fragment bases: two m16 tiles (rb*32, rb*32+16)
    const int aR = rb * 32 + (tt & 1) * 8 + tr;
    const int aK = (tt >> 1) * 8;
    const int wStride = isW0 ? SW0 : SWC;
    const uint32_t suW0 = su32(s_w0), suWc = su32(s_wc), suH = su32(s_h);
    const uint32_t aBase0 = (isW0 ? suW0 : suWc) + (uint32_t)(aR * wStride + aK) * 2;
    const uint32_t aBase1 = aBase0 + (uint32_t)(16 * wStride) * 2;
    const int bR = nh * 16 + (tt >> 1) * 8 + tr;
    const int bK = (tt & 1) * 8;
    const uint32_t bBase = suH + (uint32_t)(bR * SHH + bK) * 2;

    const int dRow = m >> 3, seg = m & 7;             // staging duties (2 CP16/chunk)
    const int bb = m >> 3, up = m & 7;                // activation mapping

    // gate rows owned by this warp: grow(a,o) for fragment rows rb*32+16a+gq+o
    const int grow00 = ((2 * rb + 0) << 9) + j0 + gq;   // a=0, o=0
    const int grow01 = grow00 + 8;                      // a=0, o=8
    const int grow10 = ((2 * rb + 1) << 9) + j0 + gq;   // a=1
    const int grow11 = grow10 + 8;

    // ===== resident weight slices =====
    for (int idx = m; idx < 4096; idx += NT) {
        int r = idx >> 6, sg = idx & 63;
        int grow = ((r >> 4) << 9) + j0 + (r & 15);
        CP16(suW0 + (uint32_t)(r * SW0 + sg * 8) * 2,
             g_Wh0h + (size_t)grow * Hd + sg * 8);
    }
    for (int idx = m; idx < 8192; idx += NT) {
        int r = idx >> 7, sg = idx & 127;
        int grow = ((r >> 4) << 9) + j0 + (r & 15);
        CP16(suWc + (uint32_t)(r * SWC + sg * 8) * 2,
             g_Wcath + (size_t)grow * (2 * Hd) + sg * 8);
    }
    asm volatile("cp.async.commit_group;\n" ::: "memory");
    asm volatile("cp.async.wait_group 0;\n" ::: "memory");
    __syncthreads();

    float c0a = 0.f, c0b = 0.f, c1a = 0.f, c1b = 0.f;
    unsigned bar = 0;

    // ===== prologue A(0) =====
    {
        const float* xg0 = g_xg;
        float gi = xg0[((size_t)(0 * Hd) + j0 + up) * Bsz + b0 + bb];
        float gg = xg0[((size_t)(2 * Hd) + j0 + up) * Bsz + b0 + bb];
        float go = xg0[((size_t)(3 * Hd) + j0 + up) * Bsz + b0 + bb];
        c0a = sigf(gi) * tanhf(gg);
        g_h0h[0][(size_t)(b0 + bb) * Hd + j0 + up] = __float2half(sigf(go) * tanhf(c0a));
        gi = xg0[((size_t)(0 * Hd) + j0 + up + 8) * Bsz + b0 + bb];
        gg = xg0[((size_t)(2 * Hd) + j0 + up + 8) * Bsz + b0 + bb];
        go = xg0[((size_t)(3 * Hd) + j0 + up + 8) * Bsz + b0 + bb];
        c0b = sigf(gi) * tanhf(gg);
        g_h0h[0][(size_t)(b0 + bb) * Hd + j0 + up + 8] = __float2half(sigf(go) * tanhf(c0b));
    }
    gridbar(bu, ++bar * 32);

    const float bv00 = __ldg(&g_bias1[grow00]);
    const float bv01 = __ldg(&g_bias1[grow01]);
    const float bv10 = __ldg(&g_bias1[grow10]);
    const float bv11 = __ldg(&g_bias1[grow11]);

    for (int t = 0; t < Tlen; ++t) {
        const __half* h0cur = g_h0h[t & 1];          // h0(t)
        const __half* h1prv = g_h1h[(t + 1) & 1];    // h1(t-1)
        __half*       h1nxt = g_h1h[t & 1];          // h1(t)
        __half*       h0nxt = g_h0h[(t + 1) & 1];    // h0(t+1)
        const int tA = (t + 1 < Tlen) ? (t + 1) : t;

        float acc[2][2][4];                          // [mtile a][n8 b][frag]
        if (isW0) {
            // init from xg[tA] fragments (layer-0 A(t+1))
            const float* xgt = g_xg + (size_t)tA * Gd * Bsz;
#pragma unroll
            for (int nt = 0; nt < 2; ++nt) {
                int col = b0 + nh * 16 + nt * 8 + 2 * tq;
                float2 v;
                v = *(const float2*)(xgt + (size_t)grow00 * Bsz + col);
                acc[0][nt][0] = v.x; acc[0][nt][1] = v.y;
                v = *(const float2*)(xgt + (size_t)grow01 * Bsz + col);
                acc[0][nt][2] = v.x; acc[0][nt][3] = v.y;
                v = *(const float2*)(xgt + (size_t)grow10 * Bsz + col);
                acc[1][nt][0] = v.x; acc[1][nt][1] = v.y;
                v = *(const float2*)(xgt + (size_t)grow11 * Bsz + col);
                acc[1][nt][2] = v.x; acc[1][nt][3] = v.y;
            }
        } else {
#pragma unroll
            for (int nt = 0; nt < 2; ++nt) {
                acc[0][nt][0] = bv00; acc[0][nt][1] = bv00;
                acc[0][nt][2] = bv01; acc[0][nt][3] = bv01;
                acc[1][nt][0] = bv10; acc[1][nt][1] = bv10;
                acc[1][nt][2] = bv11; acc[1][nt][3] = bv11;
            }
        }

        auto issue = [&](int c) {
            int st = c % 3;
            const __half* src = (c < 4) ? (h0cur + c * 128) : (h1prv + (c - 4) * 128);
            uint32_t dst = suH + (uint32_t)((st * 32 + dRow) * SHH + seg * 8) * 2;
            const __half* gsrc = src + (size_t)(b0 + dRow) * Hd + seg * 8;
            CP16(dst, gsrc);
            CP16(dst + 128, gsrc + 64);
            asm volatile("cp.async.commit_group;\n" ::: "memory");
        };

        issue(0); issue(1);
#pragma unroll 1
        for (int c = 0; c < 8; ++c) {
            if (c < 7) { asm volatile("cp.async.wait_group 1;\n" ::: "memory"); }
            else       { asm volatile("cp.async.wait_group 0;\n" ::: "memory"); }
            __syncthreads();
            if (c + 2 < 8) issue(c + 2);
            if (isW0 && c >= 4) continue;
            const uint32_t bA = bBase + (uint32_t)((c % 3) * 32 * SHH) * 2;
            const uint32_t aOff = (uint32_t)(c * 128) * 2;
#pragma unroll
            for (int ks = 0; ks < 8; ++ks) {
                uint32_t a0, a1, a2, a3, a4, a5, a6, a7, b0r, b1r, b2r, b3r;
                LDSM4(b0r, b1r, b2r, b3r, bA + ks * 32);
                LDSM4(a0, a1, a2, a3, aBase0 + aOff + ks * 32);
                LDSM4(a4, a5, a6, a7, aBase1 + aOff + ks * 32);
                MMA168(acc[0][0], a0, a1, a2, a3, b0r, b1r);
                MMA168(acc[0][1], a0, a1, a2, a3, b2r, b3r);
                MMA168(acc[1][0], a4, a5, a6, a7, b0r, b1r);
                MMA168(acc[1][1], a4, a5, a6, a7, b2r, b3r);
            }
        }

        // publish gates (swizzled stride-32): dst row r, col c -> c ^ ((r&7)<<2)
        {
            float* dst = isW0 ? s_gA : s_gB;
#pragma unroll
            for (int a = 0; a < 2; ++a) {
#pragma unroll
                for (int nt = 0; nt < 2; ++nt) {
                    int row0 = rb * 32 + 16 * a + gq;      // row0 & 7 == gq
                    int col  = nh * 16 + nt * 8 + 2 * tq;
                    int sc   = col ^ (gq << 2);
                    *(float2*)&dst[row0 * 32 + sc] = make_float2(acc[a][nt][0], acc[a][nt][1]);
                    *(float2*)&dst[(row0 + 8) * 32 + sc] = make_float2(acc[a][nt][2], acc[a][nt][3]);
                }
            }
        }
        __syncthreads();

        // ===== activations: read swizzled s_g (col bb -> bb ^ (up<<2)) =====
        {
            const int sc = bb ^ (up << 2);
            const int sc8 = bb ^ (up << 2);        // (up+8)&7 == up -> same swizzle
            // B(t) -> h1(t)
            float gi = s_gB[(0 * 16 + up) * 32 + sc];
            float gf = s_gB[(1 * 16 + up) * 32 + sc];
            float gg = s_gB[(2 * 16 + up) * 32 + sc];
            float go = s_gB[(3 * 16 + up) * 32 + sc];
            c1a = sigf(gf) * c1a + sigf(gi) * tanhf(gg);
            h1nxt[(size_t)(b0 + bb) * Hd + j0 + up] = __float2half(sigf(go) * tanhf(c1a));
            gi = s_gB[(0 * 16 + up + 8) * 32 + sc8];
            gf = s_gB[(1 * 16 + up + 8) * 32 + sc8];
            gg = s_gB[(2 * 16 + up + 8) * 32 + sc8];
            go = s_gB[(3 * 16 + up + 8) * 32 + sc8];
            c1b = sigf(gf) * c1b + sigf(gi) * tanhf(gg);
            h1nxt[(size_t)(b0 + bb) * Hd + j0 + up + 8] = __float2half(sigf(go) * tanhf(c1b));
            // A(t+1) -> h0(t+1)  (bogus-but-unused at t=1023)
            gi = s_gA[(0 * 16 + up) * 32 + sc];
            gf = s_gA[(1 * 16 + up) * 32 + sc];
            gg = s_gA[(2 * 16 + up) * 32 + sc];
            go = s_gA[(3 * 16 + up) * 32 + sc];
            c0a = sigf(gf) * c0a + sigf(gi) * tanhf(gg);
            h0nxt[(size_t)(b0 + bb) * Hd + j0 + up] = __float2half(sigf(go) * tanhf(c0a));
            gi = s_gA[(0 * 16 + up + 8) * 32 + sc8];
            gf = s_gA[(1 * 16 + up + 8) * 32 + sc8];
            gg = s_gA[(2 * 16 + up + 8) * 32 + sc8];
            go = s_gA[(3 * 16 + up + 8) * 32 + sc8];
            c0b = sigf(gf) * c0b + sigf(gi) * tanhf(gg);
            h0nxt[(size_t)(b0 + bb) * Hd + j0 + up + 8] = __float2half(sigf(go) * tanhf(c0b));
        }
        gridbar(bu, ++bar * 32);
    }

    // ===== final FC: ju==0 block of each slice handles its 32 batch rows =====
    if (ju == 0 && m < 32) {
        const __half* hf = g_h1h[1] + (size_t)(b0 + m) * Hd;
        float a = __ldg(fcb);
#pragma unroll 8
        for (int j = 0; j < Hd; ++j)
            a += __half2float(__ldcg(&hf[j])) * __ldg(&fcw[j]);
        out[b0 + m] = a;
    }
}

extern "C" void kernel_launch(void* const* d_in, const int* in_sizes, int n_in,
                              void* d_out, int out_size) {
    const float* x    = (const float*)d_in[0];
    const float* Wih0 = (const float*)d_in[1];
    const float* Whh0 = (const float*)d_in[2];
    const float* bih0 = (const float*)d_in[3];
    const float* bhh0 = (const float*)d_in[4];
    const float* Wih1 = (const float*)d_in[5];
    const float* Whh1 = (const float*)d_in[6];
    const float* bih1 = (const float*)d_in[7];
    const float* bhh1 = (const float*)d_in[8];
    const float* fcw  = (const float*)d_in[9];
    const float* fcb  = (const float*)d_in[10];
    float* out = (float*)d_out;

    cudaFuncSetAttribute(k_scan, cudaFuncAttributeMaxDynamicSharedMemorySize, SMEM_SCAN);
    cudaFuncSetAttribute(k_xgemm, cudaFuncAttributeMaxDynamicSharedMemorySize, SMEM_XG);

    k_prep<<<(Gd * 2 * Hd) / 256, 256>>>(bih0, bhh0, bih1, bhh1, Wih1, Whh1, Whh0, Wih0);

    k_xh<<<((size_t)Bsz * Tlen * Iin / 8) / 256, 256>>>(x);

    k_xgemm<<<NBLK, NT, SMEM_XG>>>();

    k_scan<<<NBLK, NT, SMEM_SCAN>>>(fcw, fcb, out);
}